// round 6
// baseline (speedup 1.0000x reference)
#include <cuda_runtime.h>
#include <cstdint>

#define NREAL 2800
#define NPADN 3000
#define FIN   8192
#define H1    256
#define H2    128
#define NE    179200
#define KCAT  512

// ---------------- scratch (device globals; no allocation allowed) ----------
// NOTE: these are referenced ONLY inside device code. Passing a __device__
// symbol as a host-side kernel argument yields the host shadow address
// (silently readable/writable via ATS on GB300) — that was the round-3..5 bug.
__device__ __align__(16) float g_acc1[NPADN * H1];     // pre-activation z
__device__ __align__(16) float g_acc2[NPADN * KCAT];   // pre-activation gates
__device__ __align__(16) float g_Acat[NPADN * KCAT];   // [z | h0 | T1]
__device__ __align__(16) float g_Bcat[KCAT * KCAT];    // [Wx; cw0; cw1]
__device__ __align__(16) float g_deg[NPADN];
__device__ __align__(16) float g_dinv[NPADN];
__device__ __align__(16) int   g_cnt[NPADN];
__device__ __align__(16) int   g_cur[NPADN];
__device__ __align__(16) int   g_off[NPADN + 4];
__device__ __align__(16) int   g_bucket[NE];
__device__ int g_is32;   // 1 if edge_index is int32, 0 if int64

// ---------------- helpers ---------------------------------------------------
__device__ __forceinline__ float sigmoidf_(float x) {
    return 1.0f / (1.0f + expf(-x));
}

// packed f32x2 ops (Blackwell)
#define PACK2(out, lo, hi) \
    asm("mov.b64 %0, {%1, %2};" : "=l"(out) : "r"(lo), "r"(hi))
#define UNPACK2(lo, hi, in) \
    asm("mov.b64 {%0, %1}, %2;" : "=r"(lo), "=r"(hi) : "l"(in))
#define FMA2(d, a, b, c) \
    asm("fma.rn.f32x2 %0, %1, %2, %3;" : "=l"(d) : "l"(a), "l"(b), "l"(c))

// load edge_index[i] regardless of underlying dtype (int32 vs int64)
__device__ __forceinline__ int load_idx(const void* ei, int i) {
    if (g_is32) return ((const int*)ei)[i];
    return (int)((const long long*)ei)[i];
}

// ---------------- dtype probe ------------------------------------------------
__global__ void k_probe(const void* p) {
    __shared__ int any;
    if (threadIdx.x == 0) any = 0;
    __syncthreads();
    const int* q = (const int*)p;
    int v = 0;
    for (int i = threadIdx.x; i < 4096; i += blockDim.x) v |= q[2 * i + 1];
    if (v) atomicOr(&any, 1);
    __syncthreads();
    if (threadIdx.x == 0) g_is32 = (any != 0) ? 1 : 0;
}

// ---------------- init ------------------------------------------------------
__global__ void k_zero() {
    const int total = NPADN * H1 + NPADN * KCAT + 3 * NPADN;
    for (int i = blockIdx.x * blockDim.x + threadIdx.x; i < total;
         i += gridDim.x * blockDim.x) {
        if (i < NPADN * H1) g_acc1[i] = 0.f;
        else if (i < NPADN * H1 + NPADN * KCAT) g_acc2[i - NPADN * H1] = 0.f;
        else {
            int j = i - NPADN * H1 - NPADN * KCAT;
            if (j < NPADN) g_deg[j] = 0.f;
            else if (j < 2 * NPADN) g_cnt[j - NPADN] = 0;
            else g_cur[j - 2 * NPADN] = 0;
        }
    }
}

// ---------------- graph preprocessing --------------------------------------
__global__ void k_edges1(const void* __restrict__ ei,
                         const float* __restrict__ ew) {
    int e = blockIdx.x * blockDim.x + threadIdx.x;
    if (e < NE) {
        int r = load_idx(ei, e);
        int c = load_idx(ei, NE + e);
        if ((unsigned)r < NPADN) atomicAdd(&g_deg[r], ew[e]);
        if ((unsigned)c < NPADN) atomicAdd(&g_cnt[c], 1);
    }
}

__global__ void k_dinv() {
    int i = blockIdx.x * blockDim.x + threadIdx.x;
    if (i < NPADN) {
        float d = g_deg[i];
        g_dinv[i] = (d > 0.f) ? rsqrtf(d) : 0.f;
    }
}

// single block, 1024 threads: exclusive scan of g_cnt[0..2999] -> g_off
__global__ void k_scan() {
    __shared__ int warp_sums[32];
    int t = threadIdx.x;
    int i0 = t * 3;
    int v0 = (i0     < NPADN) ? g_cnt[i0]     : 0;
    int v1 = (i0 + 1 < NPADN) ? g_cnt[i0 + 1] : 0;
    int v2 = (i0 + 2 < NPADN) ? g_cnt[i0 + 2] : 0;
    int s = v0 + v1 + v2;
    int lane = t & 31, warp = t >> 5;
    int x = s;
    #pragma unroll
    for (int d = 1; d < 32; d <<= 1) {
        int y = __shfl_up_sync(0xffffffffu, x, d);
        if (lane >= d) x += y;
    }
    if (lane == 31) warp_sums[warp] = x;
    __syncthreads();
    if (warp == 0) {
        int w = warp_sums[lane];
        #pragma unroll
        for (int d = 1; d < 32; d <<= 1) {
            int y = __shfl_up_sync(0xffffffffu, w, d);
            if (lane >= d) w += y;
        }
        warp_sums[lane] = w;
    }
    __syncthreads();
    int base = (x - s) + (warp > 0 ? warp_sums[warp - 1] : 0);
    if (i0     < NPADN) g_off[i0]     = base;
    if (i0 + 1 < NPADN) g_off[i0 + 1] = base + v0;
    if (i0 + 2 < NPADN) g_off[i0 + 2] = base + v0 + v1;
    if (t == 1023) g_off[NPADN] = warp_sums[31];
}

__global__ void k_edges2(const void* __restrict__ ei) {
    int e = blockIdx.x * blockDim.x + threadIdx.x;
    if (e < NE) {
        int c = load_idx(ei, NE + e);
        if ((unsigned)c < NPADN) {
            int pos = g_off[c] + atomicAdd(&g_cur[c], 1);
            if ((unsigned)pos < NE) g_bucket[pos] = e;
        }
    }
}

// T1 gather + copy h0 into Acat. block = node, thread = feature dim.
__global__ void k_T1(const void* __restrict__ ei,
                     const float* __restrict__ ew,
                     const float* __restrict__ h0) {
    int c = blockIdx.x;
    int d = threadIdx.x;
    float dc = g_dinv[c];
    float acc = 0.f;
    int p0 = g_off[c], p1 = g_off[c + 1];
    for (int p = p0; p < p1; p++) {
        int e = g_bucket[p];
        int r = load_idx(ei, e);
        if ((unsigned)r < NPADN) {
            float w = -g_dinv[r] * ew[e] * dc;
            acc = fmaf(w, h0[r * H2 + d], acc);
        }
    }
    g_Acat[c * KCAT + H1 + H2 + d] = acc;           // cols [384,512): T1
    g_Acat[c * KCAT + H1 + d] = h0[c * H2 + d];     // cols [256,384): h0
}

// B concat: rows 0-255 = Wx, 256-383 = cw0, 384-511 = cw1; col j = g*128+o
__global__ void k_buildB(const float* __restrict__ Wx,
                         const float* __restrict__ cw0,
                         const float* __restrict__ cw1) {
    int idx = blockIdx.x * blockDim.x + threadIdx.x;
    if (idx >= KCAT * KCAT) return;
    int k = idx >> 9;       // /512
    int j = idx & 511;
    int g = j >> 7;
    int o = j & 127;
    float v;
    if (k < H1)            v = Wx [g * H1 * H2 + k * H2 + o];
    else if (k < H1 + H2)  v = cw0[g * H2 * H2 + (k - H1) * H2 + o];
    else                   v = cw1[g * H2 * H2 + (k - H1 - H2) * H2 + o];
    g_Bcat[idx] = v;
}

// ---------------- fp32 (f32x2-packed) SIMT GEMM -----------------------------
// MODE 0: A = Aext (x), B = Bext (fc0_w), C = g_acc1
// MODE 1: A = g_Acat,   B = g_Bcat,       C = g_acc2
// All scratch pointers resolved IN DEVICE CODE (see note at globals).
#define TBM 128
#define TBN 64
#define TBK 16

template <int MODE>
__global__ void __launch_bounds__(256, 2)
k_gemm_f32(const float* __restrict__ Aext, const float* __restrict__ Bext,
           int M, int M_real, int N, int lda, int ldb, int klen) {
    const float* A = (MODE == 0) ? Aext : g_Acat;
    const float* B = (MODE == 0) ? Bext : g_Bcat;
    float*       C = (MODE == 0) ? g_acc1 : g_acc2;

    __shared__ __align__(16) float As_t[TBK * TBM];   // [k][m]
    __shared__ __align__(16) float Bs[TBK * TBN];     // [k][n]

    int tid = threadIdx.x;
    int tm = tid >> 4;            // 0..15 -> 8-row slab
    int tn = tid & 15;            // 0..15 -> 4-col slab
    int m0 = blockIdx.x * TBM;
    int n0 = blockIdx.y * TBN;
    int koff = blockIdx.z * klen;

    int am = tid >> 2;            // 0..63 A-load row
    int ak = (tid & 3) * 4;       // A-load k-col group
    int bk = tid >> 4;            // 0..15 B-load k-row
    int bn = (tid & 15) * 4;      // B-load n-col group

    unsigned long long acc01[8], acc23[8];
    #pragma unroll
    for (int i = 0; i < 8; i++) { acc01[i] = 0ull; acc23[i] = 0ull; }

    for (int k0 = koff; k0 < koff + klen; k0 += TBK) {
        #pragma unroll
        for (int p = 0; p < 2; p++) {
            int r = am + p * 64;
            int grow = m0 + r;
            float4 v = make_float4(0.f, 0.f, 0.f, 0.f);
            if (grow < M_real)
                v = *(const float4*)(A + (size_t)grow * lda + k0 + ak);
            As_t[(ak + 0) * TBM + r] = v.x;
            As_t[(ak + 1) * TBM + r] = v.y;
            As_t[(ak + 2) * TBM + r] = v.z;
            As_t[(ak + 3) * TBM + r] = v.w;
        }
        {
            float4 v = *(const float4*)(B + (size_t)(k0 + bk) * ldb + n0 + bn);
            *(float4*)&Bs[bk * TBN + bn] = v;
        }
        __syncthreads();

        #pragma unroll
        for (int kk = 0; kk < TBK; kk++) {
            float4 a0 = *(const float4*)&As_t[kk * TBM + tm * 8];
            float4 a1 = *(const float4*)&As_t[kk * TBM + tm * 8 + 4];
            float4 b  = *(const float4*)&Bs[kk * TBN + tn * 4];
            unsigned long long b01, b23;
            PACK2(b01, __float_as_uint(b.x), __float_as_uint(b.y));
            PACK2(b23, __float_as_uint(b.z), __float_as_uint(b.w));
            float av[8] = {a0.x, a0.y, a0.z, a0.w, a1.x, a1.y, a1.z, a1.w};
            #pragma unroll
            for (int i = 0; i < 8; i++) {
                unsigned long long aa;
                uint32_t au = __float_as_uint(av[i]);
                PACK2(aa, au, au);
                FMA2(acc01[i], aa, b01, acc01[i]);
                FMA2(acc23[i], aa, b23, acc23[i]);
            }
        }
        __syncthreads();
    }

    #pragma unroll
    for (int i = 0; i < 8; i++) {
        int row = m0 + tm * 8 + i;
        if (row < M) {
            float* cp = &C[(size_t)row * N + n0 + tn * 4];
            uint32_t lo, hi;
            UNPACK2(lo, hi, acc01[i]);
            atomicAdd(cp + 0, __uint_as_float(lo));
            atomicAdd(cp + 1, __uint_as_float(hi));
            UNPACK2(lo, hi, acc23[i]);
            atomicAdd(cp + 2, __uint_as_float(lo));
            atomicAdd(cp + 3, __uint_as_float(hi));
        }
    }
}

// ---------------- epilogue 1: z = relu(acc1 + b) -> Acat[:, 0:256] ----------
__global__ void k_epi1(const float* __restrict__ fc0_b) {
    int idx = blockIdx.x * blockDim.x + threadIdx.x;
    if (idx >= NPADN * H1) return;
    int row = idx >> 8;
    int col = idx & 255;
    float z = g_acc1[idx] + fc0_b[col];
    g_Acat[row * KCAT + col] = fmaxf(z, 0.f);
}

// ---------------- LSTM pointwise + output projection ------------------------
__global__ void k_lstm(const float* __restrict__ bg, const float* __restrict__ cb,
                       const float* __restrict__ c0,
                       const float* __restrict__ fc_w, const float* __restrict__ fc_b,
                       float* __restrict__ dout, int out_size) {
    __shared__ float red[4];
    int n = blockIdx.x;
    int o = threadIdx.x;
    const float* a = &g_acc2[(size_t)n * KCAT];
    float p0 = a[0 * H2 + o] + bg[0 * H2 + o] + cb[0 * H2 + o];
    float p1 = a[1 * H2 + o] + bg[1 * H2 + o] + cb[1 * H2 + o];
    float p2 = a[2 * H2 + o] + bg[2 * H2 + o] + cb[2 * H2 + o];
    float p3 = a[3 * H2 + o] + bg[3 * H2 + o] + cb[3 * H2 + o];
    float ig = sigmoidf_(p0);
    float fg = sigmoidf_(p1);
    float tg = tanhf(p2);
    float og = sigmoidf_(p3);
    float cn = fg * c0[n * H2 + o] + ig * tg;
    float hn = og * tanhf(cn);
    int hidx = NREAL + n * H2 + o;
    if (hidx < out_size) dout[hidx] = hn;

    float r = fmaxf(hn, 0.f) * fc_w[o];
    #pragma unroll
    for (int d = 16; d > 0; d >>= 1) r += __shfl_down_sync(0xffffffffu, r, d);
    int lane = o & 31, warp = o >> 5;
    if (lane == 0) red[warp] = r;
    __syncthreads();
    if (o == 0 && n < NREAL) {
        float s = red[0] + red[1] + red[2] + red[3] + fc_b[0];
        dout[n] = s;
    }
}

// ---------------- launch -----------------------------------------------------
extern "C" void kernel_launch(void* const* d_in, const int* in_sizes, int n_in,
                              void* d_out, int out_size) {
    const float *x = nullptr, *ew = nullptr, *h0 = nullptr, *c0 = nullptr;
    const float *fc0w = nullptr, *fc0b = nullptr, *Wx = nullptr, *bg = nullptr;
    const float *cw0 = nullptr, *cw1 = nullptr, *cb = nullptr;
    const float *fcw = nullptr, *fcb = nullptr;
    const void* ei = nullptr;

    int pos384[2] = {-1, -1};
    int i256 = -1, iBigW = -1;

    for (int i = 0; i < n_in; i++) {
        int s = in_sizes[i];
        const void* p = d_in[i];
        if (s == NREAL * FIN)      x = (const float*)p;
        else if (s == 2 * NE)      ei = p;
        else if (s == NE)          ew = (const float*)p;
        else if (s == NPADN * H2)  { if (pos384[0] < 0) pos384[0] = i; else pos384[1] = i; }
        else if (s == FIN * H1)    { fc0w = (const float*)p; iBigW = i; }
        else if (s == H1)          { fc0b = (const float*)p; i256 = i; }
        else if (s == 4 * H1 * H2) Wx = (const float*)p;
        else if (s == 4 * H2)      { if (!bg) bg = (const float*)p; else cb = (const float*)p; }
        else if (s == 4 * H2 * H2) { if (!cw0) cw0 = (const float*)p; else cw1 = (const float*)p; }
        else if (s == H2)          fcw = (const float*)p;
        else if (s == 1)           fcb = (const float*)p;
    }

    // Ordering detection: under sorted-key order, fc0_b precedes fc0_w AND
    // c0 precedes h0. Under signature/insertion order, fc0_w precedes fc0_b
    // AND h0 precedes c0. (bg/cb and cw0/cw1 keep the same relative order
    // under both.)
    bool sorted_order = (i256 >= 0 && iBigW >= 0 && i256 < iBigW);
    if (sorted_order) {
        c0 = (const float*)d_in[pos384[0]];
        h0 = (const float*)d_in[pos384[1]];
    } else {
        h0 = (const float*)d_in[pos384[0]];
        c0 = (const float*)d_in[pos384[1]];
    }

    float* out = (float*)d_out;

    // 0. probe edge_index dtype (int32 vs int64)
    k_probe<<<1, 256>>>(ei);
    // 1. zero scratch
    {
        const int total = NPADN * H1 + NPADN * KCAT + 3 * NPADN;
        k_zero<<<(total + 255) / 256, 256>>>();
    }
    // 2. graph preprocessing
    k_edges1<<<(NE + 255) / 256, 256>>>(ei, ew);
    k_dinv<<<(NPADN + 255) / 256, 256>>>();
    k_scan<<<1, 1024>>>();
    k_edges2<<<(NE + 255) / 256, 256>>>(ei);
    k_T1<<<NPADN, H2>>>(ei, ew, h0);
    // 3. big GEMM: acc1 = x_pad @ fc0_w   (M=3000, N=256, K=8192, split-K=2)
    k_gemm_f32<0><<<dim3(24, 4, 2), 256>>>(x, fc0w,
                                           NPADN, NREAL, H1, FIN, H1, FIN / 2);
    // 4. z = relu(acc1 + b) into Acat[:,0:256]
    k_epi1<<<(NPADN * H1 + 255) / 256, 256>>>(fc0b);
    // 5. gates GEMM: acc2 = Acat(3000x512) @ Bcat(512x512)
    k_buildB<<<(KCAT * KCAT + 255) / 256, 256>>>(Wx, cw0, cw1);
    k_gemm_f32<1><<<dim3(24, 8, 1), 256>>>(nullptr, nullptr,
                                           NPADN, NPADN, KCAT, KCAT, KCAT, KCAT);
    // 6. LSTM pointwise + projection
    k_lstm<<<NPADN, H2>>>(bg, cb, c0, fcw, fcb, out, out_size);
}

// round 7
// speedup vs baseline: 1.7702x; 1.7702x over previous
#include <cuda_runtime.h>
#include <cuda_bf16.h>
#include <cstdint>

#define NREAL 2800
#define NPADN 3000
#define FIN   8192
#define H1    256
#define H2    128
#define NE    179200
#define KCAT  512

// ---------------- scratch (device globals; device-code references only) ----
__device__ __align__(16) float g_acc1[NPADN * H1];
__device__ __align__(16) float g_acc2[NPADN * KCAT];
__device__ __align__(16) __nv_bfloat16 g_xhi[NREAL * FIN];
__device__ __align__(16) __nv_bfloat16 g_xlo[NREAL * FIN];
__device__ __align__(16) __nv_bfloat16 g_wThi[H1 * FIN];   // fc0_w^T [N][K]
__device__ __align__(16) __nv_bfloat16 g_wTlo[H1 * FIN];
__device__ __align__(16) __nv_bfloat16 g_Ahi[NPADN * KCAT]; // [z|h0|T1]
__device__ __align__(16) __nv_bfloat16 g_Alo[NPADN * KCAT];
__device__ __align__(16) __nv_bfloat16 g_BThi[KCAT * KCAT]; // Bcat^T [N][K]
__device__ __align__(16) __nv_bfloat16 g_BTlo[KCAT * KCAT];
__device__ __align__(16) float g_deg[NPADN];
__device__ __align__(16) float g_dinv[NPADN];
__device__ __align__(16) int   g_cnt[NPADN];
__device__ __align__(16) int   g_cur[NPADN];
__device__ __align__(16) int   g_off[NPADN + 4];
__device__ __align__(16) int   g_bucket[NE];
__device__ int g_is32;

// ---------------- helpers ---------------------------------------------------
__device__ __forceinline__ float sigmoidf_(float x) {
    return 1.0f / (1.0f + expf(-x));
}

__device__ __forceinline__ void split2(float v, __nv_bfloat16& h, __nv_bfloat16& l) {
    h = __float2bfloat16_rn(v);
    l = __float2bfloat16_rn(v - __bfloat162float(h));
}

__device__ __forceinline__ int load_idx(const void* ei, int i) {
    if (g_is32) return ((const int*)ei)[i];
    return (int)((const long long*)ei)[i];
}

__device__ __forceinline__ void mma_bf16(float* d, uint32_t a0, uint32_t a1,
                                         uint32_t a2, uint32_t a3,
                                         uint32_t b0, uint32_t b1) {
    asm volatile(
        "mma.sync.aligned.m16n8k16.row.col.f32.bf16.bf16.f32 "
        "{%0,%1,%2,%3}, {%4,%5,%6,%7}, {%8,%9}, {%0,%1,%2,%3};"
        : "+f"(d[0]), "+f"(d[1]), "+f"(d[2]), "+f"(d[3])
        : "r"(a0), "r"(a1), "r"(a2), "r"(a3), "r"(b0), "r"(b1));
}

// ---------------- dtype probe -------------------------------------------------
__global__ void k_probe(const void* p) {
    __shared__ int any;
    if (threadIdx.x == 0) any = 0;
    __syncthreads();
    const int* q = (const int*)p;
    int v = 0;
    for (int i = threadIdx.x; i < 4096; i += blockDim.x) v |= q[2 * i + 1];
    if (v) atomicOr(&any, 1);
    __syncthreads();
    if (threadIdx.x == 0) g_is32 = (any != 0) ? 1 : 0;
}

// ---------------- init --------------------------------------------------------
__global__ void k_zero() {
    const int total = NPADN * H1 + NPADN * KCAT + 3 * NPADN;
    for (int i = blockIdx.x * blockDim.x + threadIdx.x; i < total;
         i += gridDim.x * blockDim.x) {
        if (i < NPADN * H1) g_acc1[i] = 0.f;
        else if (i < NPADN * H1 + NPADN * KCAT) g_acc2[i - NPADN * H1] = 0.f;
        else {
            int j = i - NPADN * H1 - NPADN * KCAT;
            if (j < NPADN) g_deg[j] = 0.f;
            else if (j < 2 * NPADN) g_cnt[j - NPADN] = 0;
            else g_cur[j - 2 * NPADN] = 0;
        }
    }
}

// ---------------- conversions --------------------------------------------------
// x -> hi/lo bf16 (straight, row-major, pairs contiguous along K)
__global__ void k_convX(const float* __restrict__ x) {
    int i = blockIdx.x * 256 + threadIdx.x;         // float4 index
    if (i >= NREAL * FIN / 4) return;
    float4 v = ((const float4*)x)[i];
    __nv_bfloat16 h0, l0, h1, l1, h2, l2, h3, l3;
    split2(v.x, h0, l0); split2(v.y, h1, l1);
    split2(v.z, h2, l2); split2(v.w, h3, l3);
    __nv_bfloat162* ph = (__nv_bfloat162*)g_xhi;
    __nv_bfloat162* pl = (__nv_bfloat162*)g_xlo;
    ph[2 * i]     = __halves2bfloat162(h0, h1);
    ph[2 * i + 1] = __halves2bfloat162(h2, h3);
    pl[2 * i]     = __halves2bfloat162(l0, l1);
    pl[2 * i + 1] = __halves2bfloat162(l2, l3);
}

// fc0_w [FIN][H1] -> wT hi/lo [H1][FIN], smem-tiled transpose
__global__ void k_convW(const float* __restrict__ w) {
    __shared__ float tile[32][33];
    int kb = blockIdx.x * 32, jb = blockIdx.y * 32;
    int tx = threadIdx.x & 31, ty = threadIdx.x >> 5;   // 256 threads
    #pragma unroll
    for (int r = 0; r < 32; r += 8)
        tile[ty + r][tx] = w[(size_t)(kb + ty + r) * H1 + jb + tx];
    __syncthreads();
    #pragma unroll
    for (int r = 0; r < 32; r += 8) {
        float v = tile[tx][ty + r];                     // = w[kb+tx][jb+ty+r]
        __nv_bfloat16 h, l; split2(v, h, l);
        size_t o = (size_t)(jb + ty + r) * FIN + kb + tx;
        g_wThi[o] = h; g_wTlo[o] = l;
    }
}

// ---------------- graph preprocessing ------------------------------------------
__global__ void k_edges1(const void* __restrict__ ei,
                         const float* __restrict__ ew) {
    int e = blockIdx.x * blockDim.x + threadIdx.x;
    if (e < NE) {
        int r = load_idx(ei, e);
        int c = load_idx(ei, NE + e);
        if ((unsigned)r < NPADN) atomicAdd(&g_deg[r], ew[e]);
        if ((unsigned)c < NPADN) atomicAdd(&g_cnt[c], 1);
    }
}

__global__ void k_dinv() {
    int i = blockIdx.x * blockDim.x + threadIdx.x;
    if (i < NPADN) {
        float d = g_deg[i];
        g_dinv[i] = (d > 0.f) ? rsqrtf(d) : 0.f;
    }
}

__global__ void k_scan() {
    __shared__ int warp_sums[32];
    int t = threadIdx.x;
    int i0 = t * 3;
    int v0 = (i0     < NPADN) ? g_cnt[i0]     : 0;
    int v1 = (i0 + 1 < NPADN) ? g_cnt[i0 + 1] : 0;
    int v2 = (i0 + 2 < NPADN) ? g_cnt[i0 + 2] : 0;
    int s = v0 + v1 + v2;
    int lane = t & 31, warp = t >> 5;
    int x = s;
    #pragma unroll
    for (int d = 1; d < 32; d <<= 1) {
        int y = __shfl_up_sync(0xffffffffu, x, d);
        if (lane >= d) x += y;
    }
    if (lane == 31) warp_sums[warp] = x;
    __syncthreads();
    if (warp == 0) {
        int w = warp_sums[lane];
        #pragma unroll
        for (int d = 1; d < 32; d <<= 1) {
            int y = __shfl_up_sync(0xffffffffu, w, d);
            if (lane >= d) w += y;
        }
        warp_sums[lane] = w;
    }
    __syncthreads();
    int base = (x - s) + (warp > 0 ? warp_sums[warp - 1] : 0);
    if (i0     < NPADN) g_off[i0]     = base;
    if (i0 + 1 < NPADN) g_off[i0 + 1] = base + v0;
    if (i0 + 2 < NPADN) g_off[i0 + 2] = base + v0 + v1;
    if (t == 1023) g_off[NPADN] = warp_sums[31];
}

__global__ void k_edges2(const void* __restrict__ ei) {
    int e = blockIdx.x * blockDim.x + threadIdx.x;
    if (e < NE) {
        int c = load_idx(ei, NE + e);
        if ((unsigned)c < NPADN) {
            int pos = g_off[c] + atomicAdd(&g_cur[c], 1);
            if ((unsigned)pos < NE) g_bucket[pos] = e;
        }
    }
}

// T1 gather + h0 copy, writing bf16 hi/lo into A-cat directly
__global__ void k_T1(const void* __restrict__ ei,
                     const float* __restrict__ ew,
                     const float* __restrict__ h0) {
    int c = blockIdx.x;
    int d = threadIdx.x;
    float dc = g_dinv[c];
    float acc = 0.f;
    int p0 = g_off[c], p1 = g_off[c + 1];
    for (int p = p0; p < p1; p++) {
        int e = g_bucket[p];
        int r = load_idx(ei, e);
        if ((unsigned)r < NPADN) {
            float w = -g_dinv[r] * ew[e] * dc;
            acc = fmaf(w, h0[r * H2 + d], acc);
        }
    }
    __nv_bfloat16 h, l;
    float hv = h0[c * H2 + d];
    split2(hv, h, l);
    g_Ahi[c * KCAT + H1 + d] = h;             // cols [256,384): h0
    g_Alo[c * KCAT + H1 + d] = l;
    split2(acc, h, l);
    g_Ahi[c * KCAT + H1 + H2 + d] = h;        // cols [384,512): T1
    g_Alo[c * KCAT + H1 + H2 + d] = l;
}

// Bcat^T [j][k], bf16 hi/lo. j = g*128+o selects gate/output col.
__global__ void k_buildB(const float* __restrict__ Wx,
                         const float* __restrict__ cw0,
                         const float* __restrict__ cw1) {
    int idx = blockIdx.x * blockDim.x + threadIdx.x;
    if (idx >= KCAT * KCAT) return;
    int j = idx >> 9;        // output row of B^T (the N index)
    int k = idx & 511;       // K index
    int gg = j >> 7;
    int o  = j & 127;
    float v;
    if (k < H1)            v = Wx [gg * H1 * H2 + k * H2 + o];
    else if (k < H1 + H2)  v = cw0[gg * H2 * H2 + (k - H1) * H2 + o];
    else                   v = cw1[gg * H2 * H2 + (k - H1 - H2) * H2 + o];
    __nv_bfloat16 h, l; split2(v, h, l);
    g_BThi[idx] = h;         // idx = j*512 + k  (coalesced over k)
    g_BTlo[idx] = l;
}

// ---------------- bf16x2-split tensor-core GEMM --------------------------------
// C += A*B with A,B pre-split into (hi,lo) bf16; 3 MMA passes (hi*hi, hi*lo,
// lo*hi). BM=BN=128, BK=32, 256 threads (8 warps, 4x2), warp tile 32x64.
// smem rows padded to RSTR=20 uint32 -> all fragment LDS conflict-free.
#define RSTR 20

template <int MODE>
__global__ void __launch_bounds__(256, 2) k_gemm() {
    constexpr int K    = (MODE == 0) ? FIN : KCAT;
    constexpr int N    = (MODE == 0) ? H1  : KCAT;
    constexpr int MR   = (MODE == 0) ? NREAL : NPADN;
    constexpr int KLEN = (MODE == 0) ? 2048 : KCAT;
    const __nv_bfloat16* Ahi = (MODE == 0) ? g_xhi  : g_Ahi;
    const __nv_bfloat16* Alo = (MODE == 0) ? g_xlo  : g_Alo;
    const __nv_bfloat16* Bhi = (MODE == 0) ? g_wThi : g_BThi;
    const __nv_bfloat16* Blo = (MODE == 0) ? g_wTlo : g_BTlo;
    float* C = (MODE == 0) ? g_acc1 : g_acc2;

    __shared__ __align__(16) uint32_t sA[2][128 * RSTR];
    __shared__ __align__(16) uint32_t sB[2][128 * RSTR];

    int tid  = threadIdx.x;
    int warp = tid >> 5, lane = tid & 31;
    int wm = warp >> 1, wn = warp & 1;
    int g  = lane >> 2, t4 = lane & 3;
    int m0 = blockIdx.x * 128;
    int n0 = blockIdx.y * 128;
    int koff = blockIdx.z * KLEN;

    float acc[2][8][4];
    #pragma unroll
    for (int a = 0; a < 2; a++)
        #pragma unroll
        for (int b = 0; b < 8; b++)
            #pragma unroll
            for (int c = 0; c < 4; c++) acc[a][b][c] = 0.f;

    int row = tid >> 1;                 // 0..127 (A row / B row)
    int qb  = (tid & 1) * 2;            // uint4-quad base

    const uint4* A4h = (const uint4*)Ahi;
    const uint4* A4l = (const uint4*)Alo;
    const uint4* B4h = (const uint4*)Bhi;
    const uint4* B4l = (const uint4*)Blo;

    for (int k0 = koff; k0 < koff + KLEN; k0 += 32) {
        int kq = k0 >> 3;               // uint4 index along K
        // ---- A tile (128 x 32 bf16, hi+lo) ----
        {
            int grow = m0 + row;
            bool ok = grow < MR;
            #pragma unroll
            for (int j = 0; j < 2; j++) {
                uint4 vh = make_uint4(0u, 0u, 0u, 0u), vl = vh;
                if (ok) {
                    size_t s = (size_t)grow * (K / 8) + kq + qb + j;
                    vh = A4h[s]; vl = A4l[s];
                }
                *(uint4*)&sA[0][row * RSTR + (qb + j) * 4] = vh;
                *(uint4*)&sA[1][row * RSTR + (qb + j) * 4] = vl;
            }
        }
        // ---- B tile (128 n-rows x 32 bf16, hi+lo), N rows always valid ----
        {
            int nrow = n0 + row;
            #pragma unroll
            for (int j = 0; j < 2; j++) {
                size_t s = (size_t)nrow * (K / 8) + kq + qb + j;
                *(uint4*)&sB[0][row * RSTR + (qb + j) * 4] = B4h[s];
                *(uint4*)&sB[1][row * RSTR + (qb + j) * 4] = B4l[s];
            }
        }
        __syncthreads();

        #pragma unroll
        for (int ks = 0; ks < 2; ks++) {
            int pb = ks * 8 + t4;       // k-pair index within BK
            uint32_t ah[2][4], al[2][4];
            #pragma unroll
            for (int mt = 0; mt < 2; mt++) {
                int r0 = wm * 32 + mt * 16 + g;
                ah[mt][0] = sA[0][r0 * RSTR + pb];
                ah[mt][1] = sA[0][(r0 + 8) * RSTR + pb];
                ah[mt][2] = sA[0][r0 * RSTR + pb + 4];
                ah[mt][3] = sA[0][(r0 + 8) * RSTR + pb + 4];
                al[mt][0] = sA[1][r0 * RSTR + pb];
                al[mt][1] = sA[1][(r0 + 8) * RSTR + pb];
                al[mt][2] = sA[1][r0 * RSTR + pb + 4];
                al[mt][3] = sA[1][(r0 + 8) * RSTR + pb + 4];
            }
            #pragma unroll
            for (int nt = 0; nt < 8; nt++) {
                int nn = wn * 64 + nt * 8 + g;
                uint32_t bh0 = sB[0][nn * RSTR + pb];
                uint32_t bh1 = sB[0][nn * RSTR + pb + 4];
                uint32_t bl0 = sB[1][nn * RSTR + pb];
                uint32_t bl1 = sB[1][nn * RSTR + pb + 4];
                #pragma unroll
                for (int mt = 0; mt < 2; mt++) {
                    mma_bf16(acc[mt][nt], ah[mt][0], ah[mt][1], ah[mt][2], ah[mt][3], bh0, bh1);
                    mma_bf16(acc[mt][nt], ah[mt][0], ah[mt][1], ah[mt][2], ah[mt][3], bl0, bl1);
                    mma_bf16(acc[mt][nt], al[mt][0], al[mt][1], al[mt][2], al[mt][3], bh0, bh1);
                }
            }
        }
        __syncthreads();
    }

    // ---- epilogue: accumulate into C ----
    #pragma unroll
    for (int mt = 0; mt < 2; mt++)
        #pragma unroll
        for (int nt = 0; nt < 8; nt++) {
            int r0 = m0 + wm * 32 + mt * 16 + g;
            int cc = n0 + wn * 64 + nt * 8 + t4 * 2;
            if (r0 < NPADN) {
                atomicAdd(&C[(size_t)r0 * N + cc],     acc[mt][nt][0]);
                atomicAdd(&C[(size_t)r0 * N + cc + 1], acc[mt][nt][1]);
            }
            if (r0 + 8 < NPADN) {
                atomicAdd(&C[(size_t)(r0 + 8) * N + cc],     acc[mt][nt][2]);
                atomicAdd(&C[(size_t)(r0 + 8) * N + cc + 1], acc[mt][nt][3]);
            }
        }
}

// ---------------- epilogue 1: z = relu(acc1+b) -> A-cat cols [0,256) ------------
__global__ void k_epi1(const float* __restrict__ fc0_b) {
    int idx = blockIdx.x * blockDim.x + threadIdx.x;
    if (idx >= NPADN * H1) return;
    int row = idx >> 8;
    int col = idx & 255;
    float z = fmaxf(g_acc1[idx] + fc0_b[col], 0.f);
    __nv_bfloat16 h, l; split2(z, h, l);
    g_Ahi[row * KCAT + col] = h;
    g_Alo[row * KCAT + col] = l;
}

// ---------------- LSTM pointwise + output projection ----------------------------
__global__ void k_lstm(const float* __restrict__ bg, const float* __restrict__ cb,
                       const float* __restrict__ c0,
                       const float* __restrict__ fc_w, const float* __restrict__ fc_b,
                       float* __restrict__ dout, int out_size) {
    __shared__ float red[4];
    int n = blockIdx.x;
    int o = threadIdx.x;
    const float* a = &g_acc2[(size_t)n * KCAT];
    float p0 = a[0 * H2 + o] + bg[0 * H2 + o] + cb[0 * H2 + o];
    float p1 = a[1 * H2 + o] + bg[1 * H2 + o] + cb[1 * H2 + o];
    float p2 = a[2 * H2 + o] + bg[2 * H2 + o] + cb[2 * H2 + o];
    float p3 = a[3 * H2 + o] + bg[3 * H2 + o] + cb[3 * H2 + o];
    float ig = sigmoidf_(p0);
    float fg = sigmoidf_(p1);
    float tg = tanhf(p2);
    float og = sigmoidf_(p3);
    float cn = fg * c0[n * H2 + o] + ig * tg;
    float hn = og * tanhf(cn);
    int hidx = NREAL + n * H2 + o;
    if (hidx < out_size) dout[hidx] = hn;

    float r = fmaxf(hn, 0.f) * fc_w[o];
    #pragma unroll
    for (int d = 16; d > 0; d >>= 1) r += __shfl_down_sync(0xffffffffu, r, d);
    int lane = o & 31, warp = o >> 5;
    if (lane == 0) red[warp] = r;
    __syncthreads();
    if (o == 0 && n < NREAL) {
        float s = red[0] + red[1] + red[2] + red[3] + fc_b[0];
        dout[n] = s;
    }
}

// ---------------- launch ---------------------------------------------------------
extern "C" void kernel_launch(void* const* d_in, const int* in_sizes, int n_in,
                              void* d_out, int out_size) {
    const float *x = nullptr, *ew = nullptr, *h0 = nullptr, *c0 = nullptr;
    const float *fc0w = nullptr, *fc0b = nullptr, *Wx = nullptr, *bg = nullptr;
    const float *cw0 = nullptr, *cw1 = nullptr, *cb = nullptr;
    const float *fcw = nullptr, *fcb = nullptr;
    const void* ei = nullptr;

    int pos384[2] = {-1, -1};
    int i256 = -1, iBigW = -1;

    for (int i = 0; i < n_in; i++) {
        int s = in_sizes[i];
        const void* p = d_in[i];
        if (s == NREAL * FIN)      x = (const float*)p;
        else if (s == 2 * NE)      ei = p;
        else if (s == NE)          ew = (const float*)p;
        else if (s == NPADN * H2)  { if (pos384[0] < 0) pos384[0] = i; else pos384[1] = i; }
        else if (s == FIN * H1)    { fc0w = (const float*)p; iBigW = i; }
        else if (s == H1)          { fc0b = (const float*)p; i256 = i; }
        else if (s == 4 * H1 * H2) Wx = (const float*)p;
        else if (s == 4 * H2)      { if (!bg) bg = (const float*)p; else cb = (const float*)p; }
        else if (s == 4 * H2 * H2) { if (!cw0) cw0 = (const float*)p; else cw1 = (const float*)p; }
        else if (s == H2)          fcw = (const float*)p;
        else if (s == 1)           fcb = (const float*)p;
    }

    // sorted-key order => fc0_b before fc0_w and c0 before h0;
    // signature order  => the reverse for both pairs.
    bool sorted_order = (i256 >= 0 && iBigW >= 0 && i256 < iBigW);
    if (sorted_order) {
        c0 = (const float*)d_in[pos384[0]];
        h0 = (const float*)d_in[pos384[1]];
    } else {
        h0 = (const float*)d_in[pos384[0]];
        c0 = (const float*)d_in[pos384[1]];
    }

    float* out = (float*)d_out;

    k_probe<<<1, 256>>>(ei);
    {
        const int total = NPADN * H1 + NPADN * KCAT + 3 * NPADN;
        k_zero<<<(total + 255) / 256, 256>>>();
    }
    // conversions (independent of graph work)
    k_convX<<<(NREAL * FIN / 4 + 255) / 256, 256>>>(x);
    k_convW<<<dim3(FIN / 32, H1 / 32), 256>>>(fc0w);
    // graph preprocessing
    k_edges1<<<(NE + 255) / 256, 256>>>(ei, ew);
    k_dinv<<<(NPADN + 255) / 256, 256>>>();
    k_scan<<<1, 1024>>>();
    k_edges2<<<(NE + 255) / 256, 256>>>(ei);
    k_T1<<<NPADN, H2>>>(ei, ew, h0);
    // GEMM1: acc1 = x_pad @ fc0_w   (M=3000, N=256, K=8192, split-K=4)
    k_gemm<0><<<dim3(24, 2, 4), 256>>>();
    // z = relu(acc1 + b) -> A-cat cols [0,256)
    k_epi1<<<(NPADN * H1 + 255) / 256, 256>>>(fc0b);
    // gates GEMM: acc2 = Acat(3000x512) @ Bcat(512x512)
    k_buildB<<<(KCAT * KCAT + 255) / 256, 256>>>(Wx, cw0, cw1);
    k_gemm<1><<<dim3(24, 4, 1), 256>>>();
    // LSTM pointwise + projection
    k_lstm<<<NPADN, H2>>>(bg, cb, c0, fcw, fcb, out, out_size);
}

// round 8
// speedup vs baseline: 1.8314x; 1.0345x over previous
#include <cuda_runtime.h>
#include <cuda_bf16.h>
#include <cstdint>

#define NREAL 2800
#define NPADN 3000
#define FIN   8192
#define H1    256
#define H2    128
#define NE    179200
#define KCAT  512

// ---------------- scratch (device globals; device-code references only) ----
__device__ __align__(16) float g_acc1[NPADN * H1];
__device__ __align__(16) float g_acc2[NPADN * KCAT];
__device__ __align__(16) __nv_bfloat16 g_wThi[H1 * FIN];   // fc0_w^T [N][K]
__device__ __align__(16) __nv_bfloat16 g_wTlo[H1 * FIN];
__device__ __align__(16) __nv_bfloat16 g_Ahi[NPADN * KCAT]; // [z|h0|T1]
__device__ __align__(16) __nv_bfloat16 g_Alo[NPADN * KCAT];
__device__ __align__(16) __nv_bfloat16 g_BThi[KCAT * KCAT]; // Bcat^T [N][K]
__device__ __align__(16) __nv_bfloat16 g_BTlo[KCAT * KCAT];
__device__ __align__(16) float g_deg[NPADN];
__device__ __align__(16) float g_dinv[NPADN];
__device__ __align__(16) int   g_cnt[NPADN];
__device__ __align__(16) int   g_cur[NPADN];
__device__ __align__(16) int   g_off[NPADN + 4];
__device__ __align__(16) int   g_bucket[NE];
__device__ int g_is32;

// ---------------- helpers ---------------------------------------------------
__device__ __forceinline__ float sigmoidf_(float x) {
    return 1.0f / (1.0f + expf(-x));
}

__device__ __forceinline__ void split2(float v, __nv_bfloat16& h, __nv_bfloat16& l) {
    h = __float2bfloat16_rn(v);
    l = __float2bfloat16_rn(v - __bfloat162float(h));
}

// pack split of two floats -> (hi2, lo2) as uint32
__device__ __forceinline__ void split2x2(float a, float b, uint32_t& h2, uint32_t& l2) {
    __nv_bfloat16 ha, la, hb, lb;
    split2(a, ha, la); split2(b, hb, lb);
    __nv_bfloat162 h = __halves2bfloat162(ha, hb);
    __nv_bfloat162 l = __halves2bfloat162(la, lb);
    h2 = *(uint32_t*)&h; l2 = *(uint32_t*)&l;
}

__device__ __forceinline__ int load_idx(const void* ei, int i) {
    if (g_is32) return ((const int*)ei)[i];
    return (int)((const long long*)ei)[i];
}

__device__ __forceinline__ void mma_bf16(float* d, uint32_t a0, uint32_t a1,
                                         uint32_t a2, uint32_t a3,
                                         uint32_t b0, uint32_t b1) {
    asm volatile(
        "mma.sync.aligned.m16n8k16.row.col.f32.bf16.bf16.f32 "
        "{%0,%1,%2,%3}, {%4,%5,%6,%7}, {%8,%9}, {%0,%1,%2,%3};"
        : "+f"(d[0]), "+f"(d[1]), "+f"(d[2]), "+f"(d[3])
        : "r"(a0), "r"(a1), "r"(a2), "r"(a3), "r"(b0), "r"(b1));
}

// ---------------- dtype probe -------------------------------------------------
__global__ void k_probe(const void* p) {
    __shared__ int any;
    if (threadIdx.x == 0) any = 0;
    __syncthreads();
    const int* q = (const int*)p;
    int v = 0;
    for (int i = threadIdx.x; i < 4096; i += blockDim.x) v |= q[2 * i + 1];
    if (v) atomicOr(&any, 1);
    __syncthreads();
    if (threadIdx.x == 0) g_is32 = (any != 0) ? 1 : 0;
}

// ---------------- init --------------------------------------------------------
__global__ void k_zero() {
    const int total = NPADN * H1 + NPADN * KCAT + 3 * NPADN;
    for (int i = blockIdx.x * blockDim.x + threadIdx.x; i < total;
         i += gridDim.x * blockDim.x) {
        if (i < NPADN * H1) g_acc1[i] = 0.f;
        else if (i < NPADN * H1 + NPADN * KCAT) g_acc2[i - NPADN * H1] = 0.f;
        else {
            int j = i - NPADN * H1 - NPADN * KCAT;
            if (j < NPADN) g_deg[j] = 0.f;
            else if (j < 2 * NPADN) g_cnt[j - NPADN] = 0;
            else g_cur[j - 2 * NPADN] = 0;
        }
    }
}

// fc0_w [FIN][H1] -> wT hi/lo [H1][FIN], smem-tiled transpose
__global__ void k_convW(const float* __restrict__ w) {
    __shared__ float tile[32][33];
    int kb = blockIdx.x * 32, jb = blockIdx.y * 32;
    int tx = threadIdx.x & 31, ty = threadIdx.x >> 5;   // 256 threads
    #pragma unroll
    for (int r = 0; r < 32; r += 8)
        tile[ty + r][tx] = w[(size_t)(kb + ty + r) * H1 + jb + tx];
    __syncthreads();
    #pragma unroll
    for (int r = 0; r < 32; r += 8) {
        float v = tile[tx][ty + r];                     // = w[kb+tx][jb+ty+r]
        __nv_bfloat16 h, l; split2(v, h, l);
        size_t o = (size_t)(jb + ty + r) * FIN + kb + tx;
        g_wThi[o] = h; g_wTlo[o] = l;
    }
}

// ---------------- graph preprocessing ------------------------------------------
__global__ void k_edges1(const void* __restrict__ ei,
                         const float* __restrict__ ew) {
    int e = blockIdx.x * blockDim.x + threadIdx.x;
    if (e < NE) {
        int r = load_idx(ei, e);
        int c = load_idx(ei, NE + e);
        if ((unsigned)r < NPADN) atomicAdd(&g_deg[r], ew[e]);
        if ((unsigned)c < NPADN) atomicAdd(&g_cnt[c], 1);
    }
}

__global__ void k_dinv() {
    int i = blockIdx.x * blockDim.x + threadIdx.x;
    if (i < NPADN) {
        float d = g_deg[i];
        g_dinv[i] = (d > 0.f) ? rsqrtf(d) : 0.f;
    }
}

__global__ void k_scan() {
    __shared__ int warp_sums[32];
    int t = threadIdx.x;
    int i0 = t * 3;
    int v0 = (i0     < NPADN) ? g_cnt[i0]     : 0;
    int v1 = (i0 + 1 < NPADN) ? g_cnt[i0 + 1] : 0;
    int v2 = (i0 + 2 < NPADN) ? g_cnt[i0 + 2] : 0;
    int s = v0 + v1 + v2;
    int lane = t & 31, warp = t >> 5;
    int x = s;
    #pragma unroll
    for (int d = 1; d < 32; d <<= 1) {
        int y = __shfl_up_sync(0xffffffffu, x, d);
        if (lane >= d) x += y;
    }
    if (lane == 31) warp_sums[warp] = x;
    __syncthreads();
    if (warp == 0) {
        int w = warp_sums[lane];
        #pragma unroll
        for (int d = 1; d < 32; d <<= 1) {
            int y = __shfl_up_sync(0xffffffffu, w, d);
            if (lane >= d) w += y;
        }
        warp_sums[lane] = w;
    }
    __syncthreads();
    int base = (x - s) + (warp > 0 ? warp_sums[warp - 1] : 0);
    if (i0     < NPADN) g_off[i0]     = base;
    if (i0 + 1 < NPADN) g_off[i0 + 1] = base + v0;
    if (i0 + 2 < NPADN) g_off[i0 + 2] = base + v0 + v1;
    if (t == 1023) g_off[NPADN] = warp_sums[31];
}

__global__ void k_edges2(const void* __restrict__ ei) {
    int e = blockIdx.x * blockDim.x + threadIdx.x;
    if (e < NE) {
        int c = load_idx(ei, NE + e);
        if ((unsigned)c < NPADN) {
            int pos = g_off[c] + atomicAdd(&g_cur[c], 1);
            if ((unsigned)pos < NE) g_bucket[pos] = e;
        }
    }
}

// T1 gather + h0 copy, writing bf16 hi/lo into A-cat directly
__global__ void k_T1(const void* __restrict__ ei,
                     const float* __restrict__ ew,
                     const float* __restrict__ h0) {
    int c = blockIdx.x;
    int d = threadIdx.x;
    float dc = g_dinv[c];
    float acc = 0.f;
    int p0 = g_off[c], p1 = g_off[c + 1];
    for (int p = p0; p < p1; p++) {
        int e = g_bucket[p];
        int r = load_idx(ei, e);
        if ((unsigned)r < NPADN) {
            float w = -g_dinv[r] * ew[e] * dc;
            acc = fmaf(w, h0[r * H2 + d], acc);
        }
    }
    __nv_bfloat16 h, l;
    float hv = h0[c * H2 + d];
    split2(hv, h, l);
    g_Ahi[c * KCAT + H1 + d] = h;             // cols [256,384): h0
    g_Alo[c * KCAT + H1 + d] = l;
    split2(acc, h, l);
    g_Ahi[c * KCAT + H1 + H2 + d] = h;        // cols [384,512): T1
    g_Alo[c * KCAT + H1 + H2 + d] = l;
}

// Bcat^T [j][k], bf16 hi/lo. j = g*128+o selects gate/output col.
__global__ void k_buildB(const float* __restrict__ Wx,
                         const float* __restrict__ cw0,
                         const float* __restrict__ cw1) {
    int idx = blockIdx.x * blockDim.x + threadIdx.x;
    if (idx >= KCAT * KCAT) return;
    int j = idx >> 9;
    int k = idx & 511;
    int gg = j >> 7;
    int o  = j & 127;
    float v;
    if (k < H1)            v = Wx [gg * H1 * H2 + k * H2 + o];
    else if (k < H1 + H2)  v = cw0[gg * H2 * H2 + (k - H1) * H2 + o];
    else                   v = cw1[gg * H2 * H2 + (k - H1 - H2) * H2 + o];
    __nv_bfloat16 h, l; split2(v, h, l);
    g_BThi[idx] = h;
    g_BTlo[idx] = l;
}

// ---------------- bf16x2-split tensor-core GEMM, reg-prefetch pipeline ---------
// MODE 0: A = x (fp32, split in-kernel), B = wT hi/lo, C = g_acc1
// MODE 1: A = Ahi/Alo (pre-split),       B = BT hi/lo, C = g_acc2
#define RSTR 20

template <int MODE>
__global__ void __launch_bounds__(256, 2) k_gemm(const float* __restrict__ Xf) {
    constexpr int K    = (MODE == 0) ? FIN : KCAT;
    constexpr int N    = (MODE == 0) ? H1  : KCAT;
    constexpr int MR   = (MODE == 0) ? NREAL : NPADN;
    constexpr int KLEN = (MODE == 0) ? 2048 : KCAT;
    constexpr int ITERS = KLEN / 32;
    const __nv_bfloat16* Bhi = (MODE == 0) ? g_wThi : g_BThi;
    const __nv_bfloat16* Blo = (MODE == 0) ? g_wTlo : g_BTlo;
    float* C = (MODE == 0) ? g_acc1 : g_acc2;

    __shared__ __align__(16) uint32_t sA[2][128 * RSTR];   // [hi/lo]
    __shared__ __align__(16) uint32_t sB[2][128 * RSTR];

    int tid  = threadIdx.x;
    int warp = tid >> 5, lane = tid & 31;
    int wm = warp >> 1, wn = warp & 1;
    int g  = lane >> 2, t4 = lane & 3;
    int m0 = blockIdx.x * 128;
    int n0 = blockIdx.y * 128;
    int koff = blockIdx.z * KLEN;

    float acc[2][8][4];
    #pragma unroll
    for (int a = 0; a < 2; a++)
        #pragma unroll
        for (int b = 0; b < 8; b++)
            #pragma unroll
            for (int c = 0; c < 4; c++) acc[a][b][c] = 0.f;

    int row = tid >> 1;                 // 0..127
    int half = tid & 1;                 // 0/1: which 16-float half of the row
    int grow = m0 + row;
    bool aok = grow < MR;
    int nrow = n0 + row;

    const uint4* B4h = (const uint4*)Bhi;
    const uint4* B4l = (const uint4*)Blo;
    const float4* X4 = (const float4*)Xf;
    const uint4* A4h = (const uint4*)g_Ahi;
    const uint4* A4l = (const uint4*)g_Alo;

    // prefetch registers
    float4 ra[4];                       // MODE 0: fp32 A
    uint4  rah[2], ral[2];              // MODE 1: pre-split A
    uint4  rbh[2], rbl[2];

    auto load_tile = [&](int it) {
        int k0 = koff + it * 32;
        if (MODE == 0) {
            if (aok) {
                size_t base = (size_t)grow * (K / 4) + (k0 >> 2) + half * 4;
                #pragma unroll
                for (int j = 0; j < 4; j++) ra[j] = X4[base + j];
            } else {
                #pragma unroll
                for (int j = 0; j < 4; j++) ra[j] = make_float4(0.f, 0.f, 0.f, 0.f);
            }
        } else {
            if (aok) {
                size_t base = (size_t)grow * (K / 8) + (k0 >> 3) + half * 2;
                #pragma unroll
                for (int j = 0; j < 2; j++) { rah[j] = A4h[base + j]; ral[j] = A4l[base + j]; }
            } else {
                #pragma unroll
                for (int j = 0; j < 2; j++) {
                    rah[j] = make_uint4(0u, 0u, 0u, 0u); ral[j] = rah[j];
                }
            }
        }
        size_t bbase = (size_t)nrow * (K / 8) + (k0 >> 3) + half * 2;
        #pragma unroll
        for (int j = 0; j < 2; j++) { rbh[j] = B4h[bbase + j]; rbl[j] = B4l[bbase + j]; }
    };

    auto store_tile = [&]() {
        uint32_t* dstAh = &sA[0][row * RSTR + half * 8];
        uint32_t* dstAl = &sA[1][row * RSTR + half * 8];
        if (MODE == 0) {
            #pragma unroll
            for (int j = 0; j < 4; j++) {
                uint32_t h0, l0, h1, l1;
                split2x2(ra[j].x, ra[j].y, h0, l0);
                split2x2(ra[j].z, ra[j].w, h1, l1);
                dstAh[2 * j] = h0; dstAh[2 * j + 1] = h1;
                dstAl[2 * j] = l0; dstAl[2 * j + 1] = l1;
            }
        } else {
            *(uint4*)&dstAh[0] = rah[0]; *(uint4*)&dstAh[4] = rah[1];
            *(uint4*)&dstAl[0] = ral[0]; *(uint4*)&dstAl[4] = ral[1];
        }
        uint32_t* dstBh = &sB[0][row * RSTR + half * 8];
        uint32_t* dstBl = &sB[1][row * RSTR + half * 8];
        *(uint4*)&dstBh[0] = rbh[0]; *(uint4*)&dstBh[4] = rbh[1];
        *(uint4*)&dstBl[0] = rbl[0]; *(uint4*)&dstBl[4] = rbl[1];
    };

    load_tile(0);

    for (int it = 0; it < ITERS; it++) {
        store_tile();
        __syncthreads();
        if (it + 1 < ITERS) load_tile(it + 1);   // prefetch next (hidden by mma)

        #pragma unroll
        for (int ks = 0; ks < 2; ks++) {
            int pb = ks * 8 + t4;
            uint32_t ah[2][4], al[2][4];
            #pragma unroll
            for (int mt = 0; mt < 2; mt++) {
                int r0 = wm * 32 + mt * 16 + g;
                ah[mt][0] = sA[0][r0 * RSTR + pb];
                ah[mt][1] = sA[0][(r0 + 8) * RSTR + pb];
                ah[mt][2] = sA[0][r0 * RSTR + pb + 4];
                ah[mt][3] = sA[0][(r0 + 8) * RSTR + pb + 4];
                al[mt][0] = sA[1][r0 * RSTR + pb];
                al[mt][1] = sA[1][(r0 + 8) * RSTR + pb];
                al[mt][2] = sA[1][r0 * RSTR + pb + 4];
                al[mt][3] = sA[1][(r0 + 8) * RSTR + pb + 4];
            }
            #pragma unroll
            for (int nt = 0; nt < 8; nt++) {
                int nn = wn * 64 + nt * 8 + g;
                uint32_t bh0 = sB[0][nn * RSTR + pb];
                uint32_t bh1 = sB[0][nn * RSTR + pb + 4];
                uint32_t bl0 = sB[1][nn * RSTR + pb];
                uint32_t bl1 = sB[1][nn * RSTR + pb + 4];
                #pragma unroll
                for (int mt = 0; mt < 2; mt++) {
                    mma_bf16(acc[mt][nt], ah[mt][0], ah[mt][1], ah[mt][2], ah[mt][3], bh0, bh1);
                    mma_bf16(acc[mt][nt], ah[mt][0], ah[mt][1], ah[mt][2], ah[mt][3], bl0, bl1);
                    mma_bf16(acc[mt][nt], al[mt][0], al[mt][1], al[mt][2], al[mt][3], bh0, bh1);
                }
            }
        }
        __syncthreads();
    }

    #pragma unroll
    for (int mt = 0; mt < 2; mt++)
        #pragma unroll
        for (int nt = 0; nt < 8; nt++) {
            int r0 = m0 + wm * 32 + mt * 16 + g;
            int cc = n0 + wn * 64 + nt * 8 + t4 * 2;
            if (r0 < NPADN) {
                atomicAdd(&C[(size_t)r0 * N + cc],     acc[mt][nt][0]);
                atomicAdd(&C[(size_t)r0 * N + cc + 1], acc[mt][nt][1]);
            }
            if (r0 + 8 < NPADN) {
                atomicAdd(&C[(size_t)(r0 + 8) * N + cc],     acc[mt][nt][2]);
                atomicAdd(&C[(size_t)(r0 + 8) * N + cc + 1], acc[mt][nt][3]);
            }
        }
}

// ---------------- epilogue 1: z = relu(acc1+b) -> A-cat cols [0,256) ------------
__global__ void k_epi1(const float* __restrict__ fc0_b) {
    int idx = blockIdx.x * blockDim.x + threadIdx.x;
    if (idx >= NPADN * H1) return;
    int row = idx >> 8;
    int col = idx & 255;
    float z = fmaxf(g_acc1[idx] + fc0_b[col], 0.f);
    __nv_bfloat16 h, l; split2(z, h, l);
    g_Ahi[row * KCAT + col] = h;
    g_Alo[row * KCAT + col] = l;
}

// ---------------- LSTM pointwise + output projection ----------------------------
__global__ void k_lstm(const float* __restrict__ bg, const float* __restrict__ cb,
                       const float* __restrict__ c0,
                       const float* __restrict__ fc_w, const float* __restrict__ fc_b,
                       float* __restrict__ dout, int out_size) {
    __shared__ float red[4];
    int n = blockIdx.x;
    int o = threadIdx.x;
    const float* a = &g_acc2[(size_t)n * KCAT];
    float p0 = a[0 * H2 + o] + bg[0 * H2 + o] + cb[0 * H2 + o];
    float p1 = a[1 * H2 + o] + bg[1 * H2 + o] + cb[1 * H2 + o];
    float p2 = a[2 * H2 + o] + bg[2 * H2 + o] + cb[2 * H2 + o];
    float p3 = a[3 * H2 + o] + bg[3 * H2 + o] + cb[3 * H2 + o];
    float ig = sigmoidf_(p0);
    float fg = sigmoidf_(p1);
    float tg = tanhf(p2);
    float og = sigmoidf_(p3);
    float cn = fg * c0[n * H2 + o] + ig * tg;
    float hn = og * tanhf(cn);
    int hidx = NREAL + n * H2 + o;
    if (hidx < out_size) dout[hidx] = hn;

    float r = fmaxf(hn, 0.f) * fc_w[o];
    #pragma unroll
    for (int d = 16; d > 0; d >>= 1) r += __shfl_down_sync(0xffffffffu, r, d);
    int lane = o & 31, warp = o >> 5;
    if (lane == 0) red[warp] = r;
    __syncthreads();
    if (o == 0 && n < NREAL) {
        float s = red[0] + red[1] + red[2] + red[3] + fc_b[0];
        dout[n] = s;
    }
}

// ---------------- launch ---------------------------------------------------------
extern "C" void kernel_launch(void* const* d_in, const int* in_sizes, int n_in,
                              void* d_out, int out_size) {
    const float *x = nullptr, *ew = nullptr, *h0 = nullptr, *c0 = nullptr;
    const float *fc0w = nullptr, *fc0b = nullptr, *Wx = nullptr, *bg = nullptr;
    const float *cw0 = nullptr, *cw1 = nullptr, *cb = nullptr;
    const float *fcw = nullptr, *fcb = nullptr;
    const void* ei = nullptr;

    int pos384[2] = {-1, -1};
    int i256 = -1, iBigW = -1;

    for (int i = 0; i < n_in; i++) {
        int s = in_sizes[i];
        const void* p = d_in[i];
        if (s == NREAL * FIN)      x = (const float*)p;
        else if (s == 2 * NE)      ei = p;
        else if (s == NE)          ew = (const float*)p;
        else if (s == NPADN * H2)  { if (pos384[0] < 0) pos384[0] = i; else pos384[1] = i; }
        else if (s == FIN * H1)    { fc0w = (const float*)p; iBigW = i; }
        else if (s == H1)          { fc0b = (const float*)p; i256 = i; }
        else if (s == 4 * H1 * H2) Wx = (const float*)p;
        else if (s == 4 * H2)      { if (!bg) bg = (const float*)p; else cb = (const float*)p; }
        else if (s == 4 * H2 * H2) { if (!cw0) cw0 = (const float*)p; else cw1 = (const float*)p; }
        else if (s == H2)          fcw = (const float*)p;
        else if (s == 1)           fcb = (const float*)p;
    }

    bool sorted_order = (i256 >= 0 && iBigW >= 0 && i256 < iBigW);
    if (sorted_order) {
        c0 = (const float*)d_in[pos384[0]];
        h0 = (const float*)d_in[pos384[1]];
    } else {
        h0 = (const float*)d_in[pos384[0]];
        c0 = (const float*)d_in[pos384[1]];
    }

    float* out = (float*)d_out;

    k_probe<<<1, 256>>>(ei);
    {
        const int total = NPADN * H1 + NPADN * KCAT + 3 * NPADN;
        k_zero<<<(total + 255) / 256, 256>>>();
    }
    k_convW<<<dim3(FIN / 32, H1 / 32), 256>>>(fc0w);
    // graph preprocessing
    k_edges1<<<(NE + 255) / 256, 256>>>(ei, ew);
    k_dinv<<<(NPADN + 255) / 256, 256>>>();
    k_scan<<<1, 1024>>>();
    k_edges2<<<(NE + 255) / 256, 256>>>(ei);
    k_T1<<<NPADN, H2>>>(ei, ew, h0);
    // GEMM1: acc1 = x_pad @ fc0_w   (M=3000, N=256, K=8192, split-K=4)
    k_gemm<0><<<dim3(24, 2, 4), 256>>>(x);
    // z = relu(acc1 + b) -> A-cat cols [0,256)
    k_epi1<<<(NPADN * H1 + 255) / 256, 256>>>(fc0b);
    // gates GEMM: acc2 = Acat(3000x512) @ Bcat(512x512)
    k_buildB<<<(KCAT * KCAT + 255) / 256, 256>>>(Wx, cw0, cw1);
    k_gemm<1><<<dim3(24, 4, 1), 256>>>(nullptr);
    // LSTM pointwise + projection
    k_lstm<<<NPADN, H2>>>(bg, cb, c0, fcw, fcb, out, out_size);
}

// round 9
// speedup vs baseline: 2.2139x; 1.2089x over previous
#include <cuda_runtime.h>
#include <cuda_bf16.h>
#include <cstdint>

#define NREAL 2800
#define NPADN 3000
#define MPAD  3072
#define FIN   8192
#define H1    256
#define H2    128
#define NE    179200
#define KCAT  512
#define RSTR  20          // uint32 words per smem row (conflict-free pad)
#define PLANE (128 * RSTR)      // 2560 words = 10KB
#define SMEMSZ (2 * 4 * PLANE * 4)   // 2 stages x 4 planes x 10KB = 80KB

// ---------------- scratch (device-code references only!) --------------------
__device__ __align__(16) float g_part1[8 * MPAD * H1];     // GEMM1 split-K partials
__device__ __align__(16) float g_acc2[MPAD * KCAT];        // gates pre-activation
__device__ __align__(16) __nv_bfloat16 g_wThi[H1 * FIN];   // fc0_w^T [N][K]
__device__ __align__(16) __nv_bfloat16 g_wTlo[H1 * FIN];
__device__ __align__(16) __nv_bfloat16 g_Ahi[NPADN * KCAT];
__device__ __align__(16) __nv_bfloat16 g_Alo[NPADN * KCAT];
__device__ __align__(16) __nv_bfloat16 g_BThi[KCAT * KCAT];
__device__ __align__(16) __nv_bfloat16 g_BTlo[KCAT * KCAT];
__device__ __align__(16) float g_deg[NPADN];
__device__ __align__(16) float g_dinv[NPADN];
__device__ __align__(16) float g_wedge[NE];
__device__ __align__(16) int   g_cnt[NPADN];
__device__ __align__(16) int   g_cur[NPADN];
__device__ __align__(16) int   g_off[NPADN + 4];
__device__ __align__(16) int   g_bucket[NE];   // holds SOURCE NODE ids
__device__ int g_is32;

// ---------------- helpers ----------------------------------------------------
__device__ __forceinline__ float sigmoidf_(float x) { return 1.0f / (1.0f + expf(-x)); }

__device__ __forceinline__ void split2(float v, __nv_bfloat16& h, __nv_bfloat16& l) {
    h = __float2bfloat16_rn(v);
    l = __float2bfloat16_rn(v - __bfloat162float(h));
}
__device__ __forceinline__ void split2x2(float a, float b, uint32_t& h2, uint32_t& l2) {
    __nv_bfloat16 ha, la, hb, lb;
    split2(a, ha, la); split2(b, hb, lb);
    __nv_bfloat162 h = __halves2bfloat162(ha, hb);
    __nv_bfloat162 l = __halves2bfloat162(la, lb);
    h2 = *(uint32_t*)&h; l2 = *(uint32_t*)&l;
}
__device__ __forceinline__ int load_idx(const void* ei, int i) {
    if (g_is32) return ((const int*)ei)[i];
    return (int)((const long long*)ei)[i];
}
__device__ __forceinline__ void mma_bf16(float* d, const uint32_t* a,
                                         uint32_t b0, uint32_t b1) {
    asm volatile(
        "mma.sync.aligned.m16n8k16.row.col.f32.bf16.bf16.f32 "
        "{%0,%1,%2,%3}, {%4,%5,%6,%7}, {%8,%9}, {%0,%1,%2,%3};"
        : "+f"(d[0]), "+f"(d[1]), "+f"(d[2]), "+f"(d[3])
        : "r"(a[0]), "r"(a[1]), "r"(a[2]), "r"(a[3]), "r"(b0), "r"(b1));
}
#define LDMX4(r0, r1, r2, r3, a) \
    asm volatile("ldmatrix.sync.aligned.m8n8.x4.shared.b16 {%0,%1,%2,%3}, [%4];" \
                 : "=r"(r0), "=r"(r1), "=r"(r2), "=r"(r3) : "r"(a))
#define CPA16(dst, src, sz) \
    asm volatile("cp.async.ca.shared.global [%0], [%1], 16, %2;" \
                 :: "r"(dst), "l"(src), "r"(sz))
#define CPA_COMMIT() asm volatile("cp.async.commit_group;")
#define CPA_WAIT0()  asm volatile("cp.async.wait_group 0;")

// ---------------- dtype probe --------------------------------------------------
__global__ void k_probe(const void* p) {
    __shared__ int any;
    if (threadIdx.x == 0) any = 0;
    __syncthreads();
    const int* q = (const int*)p;
    int v = 0;
    for (int i = threadIdx.x; i < 4096; i += blockDim.x) v |= q[2 * i + 1];
    if (v) atomicOr(&any, 1);
    __syncthreads();
    if (threadIdx.x == 0) g_is32 = (any != 0) ? 1 : 0;
}

// ---------------- init ----------------------------------------------------------
__global__ void k_zero() {
    int i = blockIdx.x * blockDim.x + threadIdx.x;
    if (i < NPADN) { g_deg[i] = 0.f; g_cnt[i] = 0; g_cur[i] = 0; }
}

// fc0_w [FIN][H1] -> wT hi/lo [H1][FIN], smem-tiled transpose
__global__ void k_convW(const float* __restrict__ w) {
    __shared__ float tile[32][33];
    int kb = blockIdx.x * 32, jb = blockIdx.y * 32;
    int tx = threadIdx.x & 31, ty = threadIdx.x >> 5;
    #pragma unroll
    for (int r = 0; r < 32; r += 8)
        tile[ty + r][tx] = w[(size_t)(kb + ty + r) * H1 + jb + tx];
    __syncthreads();
    #pragma unroll
    for (int r = 0; r < 32; r += 8) {
        float v = tile[tx][ty + r];
        __nv_bfloat16 h, l; split2(v, h, l);
        size_t o = (size_t)(jb + ty + r) * FIN + kb + tx;
        g_wThi[o] = h; g_wTlo[o] = l;
    }
}

// ---------------- graph preprocessing -------------------------------------------
__global__ void k_edges1(const void* __restrict__ ei,
                         const float* __restrict__ ew) {
    int base = (blockIdx.x * blockDim.x + threadIdx.x) * 2;
    #pragma unroll
    for (int j = 0; j < 2; j++) {
        int e = base + j;
        if (e < NE) {
            int r = load_idx(ei, e);
            int c = load_idx(ei, NE + e);
            if ((unsigned)r < NPADN) atomicAdd(&g_deg[r], ew[e]);
            if ((unsigned)c < NPADN) atomicAdd(&g_cnt[c], 1);
        }
    }
}

__global__ void k_dinv() {
    int i = blockIdx.x * blockDim.x + threadIdx.x;
    if (i < NPADN) {
        float d = g_deg[i];
        g_dinv[i] = (d > 0.f) ? rsqrtf(d) : 0.f;
    }
}

__global__ void k_scan() {
    __shared__ int warp_sums[32];
    int t = threadIdx.x;
    int i0 = t * 3;
    int v0 = (i0     < NPADN) ? g_cnt[i0]     : 0;
    int v1 = (i0 + 1 < NPADN) ? g_cnt[i0 + 1] : 0;
    int v2 = (i0 + 2 < NPADN) ? g_cnt[i0 + 2] : 0;
    int s = v0 + v1 + v2;
    int lane = t & 31, warp = t >> 5;
    int x = s;
    #pragma unroll
    for (int d = 1; d < 32; d <<= 1) {
        int y = __shfl_up_sync(0xffffffffu, x, d);
        if (lane >= d) x += y;
    }
    if (lane == 31) warp_sums[warp] = x;
    __syncthreads();
    if (warp == 0) {
        int w = warp_sums[lane];
        #pragma unroll
        for (int d = 1; d < 32; d <<= 1) {
            int y = __shfl_up_sync(0xffffffffu, w, d);
            if (lane >= d) w += y;
        }
        warp_sums[lane] = w;
    }
    __syncthreads();
    int base = (x - s) + (warp > 0 ? warp_sums[warp - 1] : 0);
    if (i0     < NPADN) g_off[i0]     = base;
    if (i0 + 1 < NPADN) g_off[i0 + 1] = base + v0;
    if (i0 + 2 < NPADN) g_off[i0 + 2] = base + v0 + v1;
    if (t == 1023) g_off[NPADN] = warp_sums[31];
}

// bucket edges by dst, precompute w_hat = -dinv[r]*ew*dinv[c]
__global__ void k_edges2(const void* __restrict__ ei,
                         const float* __restrict__ ew) {
    int e = blockIdx.x * blockDim.x + threadIdx.x;
    if (e < NE) {
        int c = load_idx(ei, NE + e);
        int r = load_idx(ei, e);
        if ((unsigned)c < NPADN && (unsigned)r < NPADN) {
            int pos = g_off[c] + atomicAdd(&g_cur[c], 1);
            if ((unsigned)pos < NE) {
                g_bucket[pos] = r;
                g_wedge[pos]  = -g_dinv[r] * ew[e] * g_dinv[c];
            }
        }
    }
}

// T1 gather + h0 copy, writing bf16 hi/lo into A-cat
__global__ void k_T1(const float* __restrict__ h0) {
    int c = blockIdx.x;
    int d = threadIdx.x;
    float acc = 0.f;
    int p0 = g_off[c], p1 = g_off[c + 1];
    for (int p = p0; p < p1; p++) {
        int r   = g_bucket[p];
        float w = g_wedge[p];
        acc = fmaf(w, h0[r * H2 + d], acc);
    }
    __nv_bfloat16 h, l;
    split2(h0[c * H2 + d], h, l);
    g_Ahi[c * KCAT + H1 + d] = h;
    g_Alo[c * KCAT + H1 + d] = l;
    split2(acc, h, l);
    g_Ahi[c * KCAT + H1 + H2 + d] = h;
    g_Alo[c * KCAT + H1 + H2 + d] = l;
}

// Bcat^T [j][k] bf16 hi/lo
__global__ void k_buildB(const float* __restrict__ Wx,
                         const float* __restrict__ cw0,
                         const float* __restrict__ cw1) {
    int idx = blockIdx.x * blockDim.x + threadIdx.x;
    if (idx >= KCAT * KCAT) return;
    int j = idx >> 9;
    int k = idx & 511;
    int gg = j >> 7;
    int o  = j & 127;
    float v;
    if (k < H1)            v = Wx [gg * H1 * H2 + k * H2 + o];
    else if (k < H1 + H2)  v = cw0[gg * H2 * H2 + (k - H1) * H2 + o];
    else                   v = cw1[gg * H2 * H2 + (k - H1 - H2) * H2 + o];
    __nv_bfloat16 h, l; split2(v, h, l);
    g_BThi[idx] = h;
    g_BTlo[idx] = l;
}

// ---------------- bf16x2-split tensor-core GEMM ---------------------------------
// 128 threads, 4 warps 2x2, warp tile 64x64, CTA tile 128x128, BK=32.
// Double-buffered dynamic smem; cp.async for bf16 operands; MODE0 splits fp32 x
// in registers. 3 MMA passes (hh, hl, lh).
// MODE 0: A=x fp32, B=wT, C=g_part1[z]  |  MODE 1: A=Ahi/lo, B=BT, C=g_acc2
template <int MODE>
__global__ void __launch_bounds__(128, 2) k_gemm(const float* __restrict__ Xf) {
    constexpr int K    = (MODE == 0) ? FIN : KCAT;
    constexpr int N    = (MODE == 0) ? H1  : KCAT;
    constexpr int MR   = (MODE == 0) ? NREAL : NPADN;
    constexpr int KLEN = (MODE == 0) ? 1024 : KCAT;
    constexpr int ITERS = KLEN / 32;
    const __nv_bfloat16* Bhi = (MODE == 0) ? g_wThi : g_BThi;
    const __nv_bfloat16* Blo = (MODE == 0) ? g_wTlo : g_BTlo;

    extern __shared__ uint32_t smem[];
    uint32_t sbase = (uint32_t)__cvta_generic_to_shared(smem);
    // planes: [stage][0=Ahi,1=Alo,2=Bhi,3=Blo]

    int tid  = threadIdx.x;
    int warp = tid >> 5, lane = tid & 31;
    int wm = warp >> 1, wn = warp & 1;
    int g  = lane >> 2, t4 = lane & 3;
    int m0 = blockIdx.x * 128;
    int n0 = blockIdx.y * 128;
    int koff = blockIdx.z * KLEN;

    float acc[4][8][4];
    #pragma unroll
    for (int a = 0; a < 4; a++)
        #pragma unroll
        for (int b = 0; b < 8; b++)
            #pragma unroll
            for (int c = 0; c < 4; c++) acc[a][b][c] = 0.f;

    int grow = m0 + tid;                 // A row this thread loads
    bool aok = grow < MR;
    int nrow = n0 + tid;                 // B row this thread loads
    unsigned asz = aok ? 16u : 0u;

    // ldmatrix lane offsets
    int lrowA = (lane & 7) + ((lane >> 3) & 1) * 8;
    int lwrdA = (lane >> 4) * 4;
    int lrowB = (lane & 7) + (lane >> 4) * 8;
    int lwrdB = ((lane >> 3) & 1) * 4;

    float4 ra[8];                        // MODE0 fp32 A prefetch

    auto issue_loads = [&](int it, int st) {
        int k0 = koff + it * 32;
        // B hi/lo via cp.async: 4 chunks of 16B per plane
        const char* bh = (const char*)(Bhi + (size_t)nrow * K + k0);
        const char* bl = (const char*)(Blo + (size_t)nrow * K + k0);
        uint32_t db = sbase + ((st * 4 + 2) * PLANE + tid * RSTR) * 4;
        uint32_t dl = sbase + ((st * 4 + 3) * PLANE + tid * RSTR) * 4;
        #pragma unroll
        for (int j = 0; j < 4; j++) {
            CPA16(db + j * 16, bh + j * 16, 16u);
            CPA16(dl + j * 16, bl + j * 16, 16u);
        }
        if (MODE == 0) {
            const float4* X4 = (const float4*)Xf;
            size_t base = (size_t)grow * (K / 4) + (k0 >> 2);
            if (aok) {
                #pragma unroll
                for (int j = 0; j < 8; j++) ra[j] = X4[base + j];
            } else {
                #pragma unroll
                for (int j = 0; j < 8; j++) ra[j] = make_float4(0.f, 0.f, 0.f, 0.f);
            }
        } else {
            const char* ah = (const char*)(g_Ahi + (size_t)grow * K + k0);
            const char* al = (const char*)(g_Alo + (size_t)grow * K + k0);
            uint32_t dah = sbase + ((st * 4 + 0) * PLANE + tid * RSTR) * 4;
            uint32_t dal = sbase + ((st * 4 + 1) * PLANE + tid * RSTR) * 4;
            #pragma unroll
            for (int j = 0; j < 4; j++) {
                CPA16(dah + j * 16, ah + j * 16, asz);
                CPA16(dal + j * 16, al + j * 16, asz);
            }
        }
        CPA_COMMIT();
    };

    auto split_sts = [&](int st) {
        if (MODE != 0) return;
        uint32_t hw[16], lw[16];
        #pragma unroll
        for (int j = 0; j < 8; j++) {
            split2x2(ra[j].x, ra[j].y, hw[2 * j],     lw[2 * j]);
            split2x2(ra[j].z, ra[j].w, hw[2 * j + 1], lw[2 * j + 1]);
        }
        uint32_t* dh = smem + (st * 4 + 0) * PLANE + tid * RSTR;
        uint32_t* dl = smem + (st * 4 + 1) * PLANE + tid * RSTR;
        #pragma unroll
        for (int q = 0; q < 4; q++) {
            *(uint4*)(dh + q * 4) = make_uint4(hw[4 * q], hw[4 * q + 1], hw[4 * q + 2], hw[4 * q + 3]);
            *(uint4*)(dl + q * 4) = make_uint4(lw[4 * q], lw[4 * q + 1], lw[4 * q + 2], lw[4 * q + 3]);
        }
    };

    auto compute = [&](int st) {
        #pragma unroll
        for (int ks = 0; ks < 2; ks++) {
            uint32_t ah[4][4], al[4][4];
            #pragma unroll
            for (int mt = 0; mt < 4; mt++) {
                int r = wm * 64 + mt * 16 + lrowA;
                uint32_t oh = sbase + ((st * 4 + 0) * PLANE + r * RSTR + ks * 8 + lwrdA) * 4;
                uint32_t ol = sbase + ((st * 4 + 1) * PLANE + r * RSTR + ks * 8 + lwrdA) * 4;
                LDMX4(ah[mt][0], ah[mt][1], ah[mt][2], ah[mt][3], oh);
                LDMX4(al[mt][0], al[mt][1], al[mt][2], al[mt][3], ol);
            }
            #pragma unroll
            for (int np = 0; np < 4; np++) {
                int r = wn * 64 + np * 16 + lrowB;
                uint32_t oh = sbase + ((st * 4 + 2) * PLANE + r * RSTR + ks * 8 + lwrdB) * 4;
                uint32_t ol = sbase + ((st * 4 + 3) * PLANE + r * RSTR + ks * 8 + lwrdB) * 4;
                uint32_t bh0, bh1, bh2, bh3, bl0, bl1, bl2, bl3;
                LDMX4(bh0, bh1, bh2, bh3, oh);
                LDMX4(bl0, bl1, bl2, bl3, ol);
                #pragma unroll
                for (int mt = 0; mt < 4; mt++) {
                    mma_bf16(acc[mt][2 * np],     ah[mt], bh0, bh1);
                    mma_bf16(acc[mt][2 * np],     ah[mt], bl0, bl1);
                    mma_bf16(acc[mt][2 * np],     al[mt], bh0, bh1);
                    mma_bf16(acc[mt][2 * np + 1], ah[mt], bh2, bh3);
                    mma_bf16(acc[mt][2 * np + 1], ah[mt], bl2, bl3);
                    mma_bf16(acc[mt][2 * np + 1], al[mt], bh2, bh3);
                }
            }
        }
    };

    // prologue
    issue_loads(0, 0);
    split_sts(0);
    CPA_WAIT0();
    __syncthreads();

    for (int it = 0; it < ITERS; it++) {
        int cur = it & 1;
        if (it + 1 < ITERS) issue_loads(it + 1, cur ^ 1);
        compute(cur);
        if (it + 1 < ITERS) split_sts(cur ^ 1);
        CPA_WAIT0();
        __syncthreads();
    }

    // epilogue: plain stores (no atomics)
    float* C = (MODE == 0) ? (g_part1 + (size_t)blockIdx.z * MPAD * H1) : g_acc2;
    #pragma unroll
    for (int mt = 0; mt < 4; mt++)
        #pragma unroll
        for (int nt = 0; nt < 8; nt++) {
            int r0 = m0 + wm * 64 + mt * 16 + g;
            int cc = n0 + wn * 64 + nt * 8 + t4 * 2;
            *(float2*)&C[(size_t)r0 * N + cc]       = make_float2(acc[mt][nt][0], acc[mt][nt][1]);
            *(float2*)&C[(size_t)(r0 + 8) * N + cc] = make_float2(acc[mt][nt][2], acc[mt][nt][3]);
        }
}

// ---------------- epilogue 1: reduce partials + bias + relu + split -------------
__global__ void k_epi1(const float* __restrict__ fc0_b) {
    int idx = blockIdx.x * blockDim.x + threadIdx.x;   // float4 units
    if (idx >= NPADN * H1 / 4) return;
    int row = idx >> 6;
    int c4  = (idx & 63) * 4;
    float4 s = make_float4(0.f, 0.f, 0.f, 0.f);
    #pragma unroll
    for (int z = 0; z < 8; z++) {
        float4 p = *(const float4*)&g_part1[(size_t)z * MPAD * H1 + row * H1 + c4];
        s.x += p.x; s.y += p.y; s.z += p.z; s.w += p.w;
    }
    float4 b = *(const float4*)&fc0_b[c4];
    float z0 = fmaxf(s.x + b.x, 0.f), z1 = fmaxf(s.y + b.y, 0.f);
    float z2 = fmaxf(s.z + b.z, 0.f), z3 = fmaxf(s.w + b.w, 0.f);
    uint32_t h0, l0, h1, l1;
    split2x2(z0, z1, h0, l0);
    split2x2(z2, z3, h1, l1);
    *(uint2*)&g_Ahi[row * KCAT + c4] = make_uint2(h0, h1);
    *(uint2*)&g_Alo[row * KCAT + c4] = make_uint2(l0, l1);
}

// ---------------- LSTM pointwise + output projection -----------------------------
__global__ void k_lstm(const float* __restrict__ bg, const float* __restrict__ cb,
                       const float* __restrict__ c0,
                       const float* __restrict__ fc_w, const float* __restrict__ fc_b,
                       float* __restrict__ dout, int out_size) {
    __shared__ float red[4];
    int n = blockIdx.x;
    int o = threadIdx.x;
    const float* a = &g_acc2[(size_t)n * KCAT];
    float p0 = a[0 * H2 + o] + bg[0 * H2 + o] + cb[0 * H2 + o];
    float p1 = a[1 * H2 + o] + bg[1 * H2 + o] + cb[1 * H2 + o];
    float p2 = a[2 * H2 + o] + bg[2 * H2 + o] + cb[2 * H2 + o];
    float p3 = a[3 * H2 + o] + bg[3 * H2 + o] + cb[3 * H2 + o];
    float ig = sigmoidf_(p0);
    float fg = sigmoidf_(p1);
    float tg = tanhf(p2);
    float og = sigmoidf_(p3);
    float cn = fg * c0[n * H2 + o] + ig * tg;
    float hn = og * tanhf(cn);
    int hidx = NREAL + n * H2 + o;
    if (hidx < out_size) dout[hidx] = hn;

    float r = fmaxf(hn, 0.f) * fc_w[o];
    #pragma unroll
    for (int d = 16; d > 0; d >>= 1) r += __shfl_down_sync(0xffffffffu, r, d);
    int lane = o & 31, warp = o >> 5;
    if (lane == 0) red[warp] = r;
    __syncthreads();
    if (o == 0 && n < NREAL) {
        float s = red[0] + red[1] + red[2] + red[3] + fc_b[0];
        dout[n] = s;
    }
}

// ---------------- launch -----------------------------------------------------------
extern "C" void kernel_launch(void* const* d_in, const int* in_sizes, int n_in,
                              void* d_out, int out_size) {
    const float *x = nullptr, *ew = nullptr, *h0 = nullptr, *c0 = nullptr;
    const float *fc0w = nullptr, *fc0b = nullptr, *Wx = nullptr, *bg = nullptr;
    const float *cw0 = nullptr, *cw1 = nullptr, *cb = nullptr;
    const float *fcw = nullptr, *fcb = nullptr;
    const void* ei = nullptr;

    int pos384[2] = {-1, -1};
    int i256 = -1, iBigW = -1;

    for (int i = 0; i < n_in; i++) {
        int s = in_sizes[i];
        const void* p = d_in[i];
        if (s == NREAL * FIN)      x = (const float*)p;
        else if (s == 2 * NE)      ei = p;
        else if (s == NE)          ew = (const float*)p;
        else if (s == NPADN * H2)  { if (pos384[0] < 0) pos384[0] = i; else pos384[1] = i; }
        else if (s == FIN * H1)    { fc0w = (const float*)p; iBigW = i; }
        else if (s == H1)          { fc0b = (const float*)p; i256 = i; }
        else if (s == 4 * H1 * H2) Wx = (const float*)p;
        else if (s == 4 * H2)      { if (!bg) bg = (const float*)p; else cb = (const float*)p; }
        else if (s == 4 * H2 * H2) { if (!cw0) cw0 = (const float*)p; else cw1 = (const float*)p; }
        else if (s == H2)          fcw = (const float*)p;
        else if (s == 1)           fcb = (const float*)p;
    }

    bool sorted_order = (i256 >= 0 && iBigW >= 0 && i256 < iBigW);
    if (sorted_order) {
        c0 = (const float*)d_in[pos384[0]];
        h0 = (const float*)d_in[pos384[1]];
    } else {
        h0 = (const float*)d_in[pos384[0]];
        c0 = (const float*)d_in[pos384[1]];
    }

    float* out = (float*)d_out;

    cudaFuncSetAttribute(k_gemm<0>, cudaFuncAttributeMaxDynamicSharedMemorySize, SMEMSZ);
    cudaFuncSetAttribute(k_gemm<1>, cudaFuncAttributeMaxDynamicSharedMemorySize, SMEMSZ);

    // launch order chosen so k_gemm<0> is the 4th launch (ncu profile slot)
    k_probe<<<1, 256>>>(ei);                                   // 0
    k_zero<<<(NPADN + 255) / 256, 256>>>();                    // 1
    k_convW<<<dim3(FIN / 32, H1 / 32), 256>>>(fc0w);           // 2
    k_gemm<0><<<dim3(24, 2, 8), 128, SMEMSZ>>>(x);             // 3  <- profiled
    k_edges1<<<(NE / 2 + 255) / 256, 256>>>(ei, ew);           // 4
    k_dinv<<<(NPADN + 255) / 256, 256>>>();                    // 5
    k_scan<<<1, 1024>>>();                                     // 6
    k_edges2<<<(NE + 255) / 256, 256>>>(ei, ew);               // 7
    k_T1<<<NPADN, H2>>>(h0);                                   // 8
    k_epi1<<<(NPADN * H1 / 4 + 255) / 256, 256>>>(fc0b);       // 9
    k_buildB<<<(KCAT * KCAT + 255) / 256, 256>>>(Wx, cw0, cw1);// 10
    k_gemm<1><<<dim3(24, 4, 1), 128, SMEMSZ>>>(nullptr);       // 11
    k_lstm<<<NPADN, H2>>>(bg, cb, c0, fcw, fcb, out, out_size);// 12
}

// round 10
// speedup vs baseline: 2.6209x; 1.1838x over previous
#include <cuda_runtime.h>
#include <cuda_bf16.h>
#include <cstdint>

#define NREAL 2800
#define NPADN 3000
#define MPAD  3072
#define FIN   8192
#define H1    256
#define H2    128
#define NE    179200
#define KCAT  512
#define RSTR  20                 // uint32 words per smem row (conflict-free)
#define PLANE (128 * RSTR)       // 2560 words = 10KB
#define SMEMSZ (2 * 4 * PLANE * 4)   // 2 stages x 4 planes x 10KB = 80KB

// ---------------- scratch (device-code references only!) --------------------
__device__ __align__(16) float g_part1[3 * MPAD * H1];     // GEMM1 split-K partials
__device__ __align__(16) float g_acc2[MPAD * KCAT];
__device__ __align__(16) __nv_bfloat16 g_wThi[H1 * FIN];
__device__ __align__(16) __nv_bfloat16 g_wTlo[H1 * FIN];
__device__ __align__(16) __nv_bfloat16 g_Ahi[NPADN * KCAT];
__device__ __align__(16) __nv_bfloat16 g_Alo[NPADN * KCAT];
__device__ __align__(16) __nv_bfloat16 g_BThi[KCAT * KCAT];
__device__ __align__(16) __nv_bfloat16 g_BTlo[KCAT * KCAT];
__device__ __align__(16) float g_deg[NPADN];
__device__ __align__(16) float g_dinv[NPADN];
__device__ __align__(16) float g_wedge[NE];
__device__ __align__(16) int   g_cnt[NPADN];
__device__ __align__(16) int   g_cur[NPADN];
__device__ __align__(16) int   g_off[NPADN + 4];
__device__ __align__(16) int   g_bucket[NE];   // SOURCE node ids
__device__ int g_is32;

// ---------------- helpers ----------------------------------------------------
__device__ __forceinline__ float sigmoidf_(float x) { return 1.0f / (1.0f + expf(-x)); }

__device__ __forceinline__ void split2(float v, __nv_bfloat16& h, __nv_bfloat16& l) {
    h = __float2bfloat16_rn(v);
    l = __float2bfloat16_rn(v - __bfloat162float(h));
}
__device__ __forceinline__ void split2x2(float a, float b, uint32_t& h2, uint32_t& l2) {
    __nv_bfloat16 ha, la, hb, lb;
    split2(a, ha, la); split2(b, hb, lb);
    __nv_bfloat162 h = __halves2bfloat162(ha, hb);
    __nv_bfloat162 l = __halves2bfloat162(la, lb);
    h2 = *(uint32_t*)&h; l2 = *(uint32_t*)&l;
}
__device__ __forceinline__ int load_idx(const void* ei, int i) {
    if (g_is32) return ((const int*)ei)[i];
    return (int)((const long long*)ei)[i];
}
__device__ __forceinline__ void mma_bf16(float* d, const uint32_t* a,
                                         uint32_t b0, uint32_t b1) {
    asm volatile(
        "mma.sync.aligned.m16n8k16.row.col.f32.bf16.bf16.f32 "
        "{%0,%1,%2,%3}, {%4,%5,%6,%7}, {%8,%9}, {%0,%1,%2,%3};"
        : "+f"(d[0]), "+f"(d[1]), "+f"(d[2]), "+f"(d[3])
        : "r"(a[0]), "r"(a[1]), "r"(a[2]), "r"(a[3]), "r"(b0), "r"(b1));
}
#define LDMX4(r0, r1, r2, r3, a) \
    asm volatile("ldmatrix.sync.aligned.m8n8.x4.shared.b16 {%0,%1,%2,%3}, [%4];" \
                 : "=r"(r0), "=r"(r1), "=r"(r2), "=r"(r3) : "r"(a))
#define CPA16(dst, src, sz) \
    asm volatile("cp.async.ca.shared.global [%0], [%1], 16, %2;" \
                 :: "r"(dst), "l"(src), "r"(sz))
#define CPA_COMMIT() asm volatile("cp.async.commit_group;")
#define CPA_WAIT0()  asm volatile("cp.async.wait_group 0;")

// ---------------- probe + zero (fused) -----------------------------------------
__global__ void k_probe_zero(const void* p) {
    int i = blockIdx.x * blockDim.x + threadIdx.x;
    if (i < NPADN) { g_deg[i] = 0.f; g_cnt[i] = 0; g_cur[i] = 0; }
    if (blockIdx.x == 0) {
        __shared__ int any;
        if (threadIdx.x == 0) any = 0;
        __syncthreads();
        const int* q = (const int*)p;
        int v = 0;
        for (int j = threadIdx.x; j < 4096; j += blockDim.x) v |= q[2 * j + 1];
        if (v) atomicOr(&any, 1);
        __syncthreads();
        if (threadIdx.x == 0) g_is32 = (any != 0) ? 1 : 0;
    }
}

// fc0_w [FIN][H1] -> wT hi/lo [H1][FIN]
__global__ void k_convW(const float* __restrict__ w) {
    __shared__ float tile[32][33];
    int kb = blockIdx.x * 32, jb = blockIdx.y * 32;
    int tx = threadIdx.x & 31, ty = threadIdx.x >> 5;
    #pragma unroll
    for (int r = 0; r < 32; r += 8)
        tile[ty + r][tx] = w[(size_t)(kb + ty + r) * H1 + jb + tx];
    __syncthreads();
    #pragma unroll
    for (int r = 0; r < 32; r += 8) {
        float v = tile[tx][ty + r];
        __nv_bfloat16 h, l; split2(v, h, l);
        size_t o = (size_t)(jb + ty + r) * FIN + kb + tx;
        g_wThi[o] = h; g_wTlo[o] = l;
    }
}

// ---------------- graph preprocessing ------------------------------------------
__global__ void k_edges1(const void* __restrict__ ei,
                         const float* __restrict__ ew) {
    int base = (blockIdx.x * blockDim.x + threadIdx.x) * 2;
    #pragma unroll
    for (int j = 0; j < 2; j++) {
        int e = base + j;
        if (e < NE) {
            int r = load_idx(ei, e);
            int c = load_idx(ei, NE + e);
            if ((unsigned)r < NPADN) atomicAdd(&g_deg[r], ew[e]);
            if ((unsigned)c < NPADN) atomicAdd(&g_cnt[c], 1);
        }
    }
}

// dinv (fused) + exclusive scan of g_cnt -> g_off; single block 1024 threads
__global__ void k_scan() {
    int t = threadIdx.x;
    for (int i = t; i < NPADN; i += 1024) {
        float d = g_deg[i];
        g_dinv[i] = (d > 0.f) ? rsqrtf(d) : 0.f;
    }
    __shared__ int warp_sums[32];
    int i0 = t * 3;
    int v0 = (i0     < NPADN) ? g_cnt[i0]     : 0;
    int v1 = (i0 + 1 < NPADN) ? g_cnt[i0 + 1] : 0;
    int v2 = (i0 + 2 < NPADN) ? g_cnt[i0 + 2] : 0;
    int s = v0 + v1 + v2;
    int lane = t & 31, warp = t >> 5;
    int x = s;
    #pragma unroll
    for (int d = 1; d < 32; d <<= 1) {
        int y = __shfl_up_sync(0xffffffffu, x, d);
        if (lane >= d) x += y;
    }
    if (lane == 31) warp_sums[warp] = x;
    __syncthreads();
    if (warp == 0) {
        int w = warp_sums[lane];
        #pragma unroll
        for (int d = 1; d < 32; d <<= 1) {
            int y = __shfl_up_sync(0xffffffffu, w, d);
            if (lane >= d) w += y;
        }
        warp_sums[lane] = w;
    }
    __syncthreads();
    int base = (x - s) + (warp > 0 ? warp_sums[warp - 1] : 0);
    if (i0     < NPADN) g_off[i0]     = base;
    if (i0 + 1 < NPADN) g_off[i0 + 1] = base + v0;
    if (i0 + 2 < NPADN) g_off[i0 + 2] = base + v0 + v1;
    if (t == 1023) g_off[NPADN] = warp_sums[31];
}

__global__ void k_edges2(const void* __restrict__ ei,
                         const float* __restrict__ ew) {
    int e = blockIdx.x * blockDim.x + threadIdx.x;
    if (e < NE) {
        int c = load_idx(ei, NE + e);
        int r = load_idx(ei, e);
        if ((unsigned)c < NPADN && (unsigned)r < NPADN) {
            int pos = g_off[c] + atomicAdd(&g_cur[c], 1);
            if ((unsigned)pos < NE) {
                g_bucket[pos] = r;
                g_wedge[pos]  = -g_dinv[r] * ew[e] * g_dinv[c];
            }
        }
    }
}

__global__ void k_T1(const float* __restrict__ h0) {
    int c = blockIdx.x;
    int d = threadIdx.x;
    float acc = 0.f;
    int p0 = g_off[c], p1 = g_off[c + 1];
    for (int p = p0; p < p1; p++)
        acc = fmaf(g_wedge[p], h0[g_bucket[p] * H2 + d], acc);
    __nv_bfloat16 h, l;
    split2(h0[c * H2 + d], h, l);
    g_Ahi[c * KCAT + H1 + d] = h;
    g_Alo[c * KCAT + H1 + d] = l;
    split2(acc, h, l);
    g_Ahi[c * KCAT + H1 + H2 + d] = h;
    g_Alo[c * KCAT + H1 + H2 + d] = l;
}

__global__ void k_buildB(const float* __restrict__ Wx,
                         const float* __restrict__ cw0,
                         const float* __restrict__ cw1) {
    int idx = blockIdx.x * blockDim.x + threadIdx.x;
    if (idx >= KCAT * KCAT) return;
    int j = idx >> 9;
    int k = idx & 511;
    int gg = j >> 7;
    int o  = j & 127;
    float v;
    if (k < H1)            v = Wx [gg * H1 * H2 + k * H2 + o];
    else if (k < H1 + H2)  v = cw0[gg * H2 * H2 + (k - H1) * H2 + o];
    else                   v = cw1[gg * H2 * H2 + (k - H1 - H2) * H2 + o];
    __nv_bfloat16 h, l; split2(v, h, l);
    g_BThi[idx] = h;
    g_BTlo[idx] = l;
}

// ---------------- bf16x2-split tensor-core GEMM ---------------------------------
// 256 threads, 8 warps (4x2 m-x-n), warp tile 32x64, CTA 128x128, BK=32,
// double-buffered cp.async, ldmatrix.x4, 3 MMA passes.
// MODE 0: A=x fp32 (reg-split), B=wT,  C=g_part1[z], uneven split-K=3
// MODE 1: A=Ahi/lo,             B=BT,  C=g_acc2
template <int MODE>
__global__ void __launch_bounds__(256, 1) k_gemm(const float* __restrict__ Xf) {
    constexpr int K  = (MODE == 0) ? FIN : KCAT;
    constexpr int N  = (MODE == 0) ? H1  : KCAT;
    constexpr int MR = (MODE == 0) ? NREAL : NPADN;
    const __nv_bfloat16* Bhi = (MODE == 0) ? g_wThi : g_BThi;
    const __nv_bfloat16* Blo = (MODE == 0) ? g_wTlo : g_BTlo;

    extern __shared__ uint32_t smem[];
    uint32_t sbase = (uint32_t)__cvta_generic_to_shared(smem);

    int tid  = threadIdx.x;
    int warp = tid >> 5, lane = tid & 31;
    int wm = warp >> 1, wn = warp & 1;
    int g  = lane >> 2, t4 = lane & 3;
    int m0 = blockIdx.x * 128;
    int n0 = blockIdx.y * 128;
    int koff, iters;
    if (MODE == 0) { koff = blockIdx.z * 2720; iters = (blockIdx.z == 2) ? 86 : 85; }
    else           { koff = 0; iters = KCAT / 32; }

    float acc[2][8][4];
    #pragma unroll
    for (int a = 0; a < 2; a++)
        #pragma unroll
        for (int b = 0; b < 8; b++)
            #pragma unroll
            for (int c = 0; c < 4; c++) acc[a][b][c] = 0.f;

    // loader mappings
    int xrow  = tid >> 1,  xhalf = tid & 1;          // MODE0 x: 256 thr, half-rows
    int prow  = tid & 127, ppl   = tid >> 7;         // cp.async: plane + row
    int xg    = m0 + xrow;  bool xok = xg < MR;
    int ag    = m0 + prow;  bool aok = ag < MR;
    unsigned asz = aok ? 16u : 0u;

    int lrowA = (lane & 7) + ((lane >> 3) & 1) * 8;
    int lwrdA = (lane >> 4) * 4;
    int lrowB = (lane & 7) + (lane >> 4) * 8;
    int lwrdB = ((lane >> 3) & 1) * 4;

    float4 ra[4];

    auto issue_loads = [&](int it, int st) {
        int k0 = koff + it * 32;
        // B planes via cp.async (each thread: one row of one plane, 64B)
        {
            const __nv_bfloat16* src = (ppl ? Blo : Bhi) + (size_t)(n0 + prow) * K + k0;
            uint32_t dst = sbase + ((st * 4 + 2 + ppl) * PLANE + prow * RSTR) * 4;
            #pragma unroll
            for (int j = 0; j < 4; j++) CPA16(dst + j * 16, (const char*)src + j * 16, 16u);
        }
        if (MODE == 0) {
            const float4* X4 = (const float4*)Xf;
            if (xok) {
                size_t base = (size_t)xg * (K / 4) + (k0 >> 2) + xhalf * 4;
                #pragma unroll
                for (int j = 0; j < 4; j++) ra[j] = X4[base + j];
            } else {
                #pragma unroll
                for (int j = 0; j < 4; j++) ra[j] = make_float4(0.f, 0.f, 0.f, 0.f);
            }
        } else {
            const __nv_bfloat16* src = (ppl ? g_Alo : g_Ahi) + (size_t)ag * K + k0;
            uint32_t dst = sbase + ((st * 4 + ppl) * PLANE + prow * RSTR) * 4;
            #pragma unroll
            for (int j = 0; j < 4; j++) CPA16(dst + j * 16, (const char*)src + j * 16, asz);
        }
        CPA_COMMIT();
    };

    auto split_sts = [&](int st) {
        if (MODE != 0) return;
        uint32_t hw[8], lw[8];
        #pragma unroll
        for (int j = 0; j < 4; j++) {
            split2x2(ra[j].x, ra[j].y, hw[2 * j],     lw[2 * j]);
            split2x2(ra[j].z, ra[j].w, hw[2 * j + 1], lw[2 * j + 1]);
        }
        uint32_t* dh = smem + (st * 4 + 0) * PLANE + xrow * RSTR + xhalf * 8;
        uint32_t* dl = smem + (st * 4 + 1) * PLANE + xrow * RSTR + xhalf * 8;
        *(uint4*)(dh)     = make_uint4(hw[0], hw[1], hw[2], hw[3]);
        *(uint4*)(dh + 4) = make_uint4(hw[4], hw[5], hw[6], hw[7]);
        *(uint4*)(dl)     = make_uint4(lw[0], lw[1], lw[2], lw[3]);
        *(uint4*)(dl + 4) = make_uint4(lw[4], lw[5], lw[6], lw[7]);
    };

    auto compute = [&](int st) {
        #pragma unroll
        for (int ks = 0; ks < 2; ks++) {
            uint32_t ah[2][4], al[2][4];
            #pragma unroll
            for (int mt = 0; mt < 2; mt++) {
                int r = wm * 32 + mt * 16 + lrowA;
                uint32_t oh = sbase + ((st * 4 + 0) * PLANE + r * RSTR + ks * 8 + lwrdA) * 4;
                uint32_t ol = sbase + ((st * 4 + 1) * PLANE + r * RSTR + ks * 8 + lwrdA) * 4;
                LDMX4(ah[mt][0], ah[mt][1], ah[mt][2], ah[mt][3], oh);
                LDMX4(al[mt][0], al[mt][1], al[mt][2], al[mt][3], ol);
            }
            #pragma unroll
            for (int np = 0; np < 4; np++) {
                int r = wn * 64 + np * 16 + lrowB;
                uint32_t oh = sbase + ((st * 4 + 2) * PLANE + r * RSTR + ks * 8 + lwrdB) * 4;
                uint32_t ol = sbase + ((st * 4 + 3) * PLANE + r * RSTR + ks * 8 + lwrdB) * 4;
                uint32_t bh0, bh1, bh2, bh3, bl0, bl1, bl2, bl3;
                LDMX4(bh0, bh1, bh2, bh3, oh);
                LDMX4(bl0, bl1, bl2, bl3, ol);
                #pragma unroll
                for (int mt = 0; mt < 2; mt++) {
                    mma_bf16(acc[mt][2 * np],     ah[mt], bh0, bh1);
                    mma_bf16(acc[mt][2 * np],     ah[mt], bl0, bl1);
                    mma_bf16(acc[mt][2 * np],     al[mt], bh0, bh1);
                    mma_bf16(acc[mt][2 * np + 1], ah[mt], bh2, bh3);
                    mma_bf16(acc[mt][2 * np + 1], ah[mt], bl2, bl3);
                    mma_bf16(acc[mt][2 * np + 1], al[mt], bh2, bh3);
                }
            }
        }
    };

    issue_loads(0, 0);
    split_sts(0);
    CPA_WAIT0();
    __syncthreads();

    for (int it = 0; it < iters; it++) {
        int cur = it & 1;
        if (it + 1 < iters) issue_loads(it + 1, cur ^ 1);
        compute(cur);
        if (it + 1 < iters) split_sts(cur ^ 1);
        CPA_WAIT0();
        __syncthreads();
    }

    float* C = (MODE == 0) ? (g_part1 + (size_t)blockIdx.z * MPAD * H1) : g_acc2;
    #pragma unroll
    for (int mt = 0; mt < 2; mt++)
        #pragma unroll
        for (int nt = 0; nt < 8; nt++) {
            int r0 = m0 + wm * 32 + mt * 16 + g;
            int cc = n0 + wn * 64 + nt * 8 + t4 * 2;
            *(float2*)&C[(size_t)r0 * N + cc]       = make_float2(acc[mt][nt][0], acc[mt][nt][1]);
            *(float2*)&C[(size_t)(r0 + 8) * N + cc] = make_float2(acc[mt][nt][2], acc[mt][nt][3]);
        }
}

// ---------------- epilogue 1: reduce 3 partials + bias + relu + split ------------
__global__ void k_epi1(const float* __restrict__ fc0_b) {
    int idx = blockIdx.x * blockDim.x + threadIdx.x;
    if (idx >= NPADN * H1 / 4) return;
    int row = idx >> 6;
    int c4  = (idx & 63) * 4;
    float4 s = make_float4(0.f, 0.f, 0.f, 0.f);
    #pragma unroll
    for (int z = 0; z < 3; z++) {
        float4 p = *(const float4*)&g_part1[(size_t)z * MPAD * H1 + row * H1 + c4];
        s.x += p.x; s.y += p.y; s.z += p.z; s.w += p.w;
    }
    float4 b = *(const float4*)&fc0_b[c4];
    float z0 = fmaxf(s.x + b.x, 0.f), z1 = fmaxf(s.y + b.y, 0.f);
    float z2 = fmaxf(s.z + b.z, 0.f), z3 = fmaxf(s.w + b.w, 0.f);
    uint32_t h0, l0, h1, l1;
    split2x2(z0, z1, h0, l0);
    split2x2(z2, z3, h1, l1);
    *(uint2*)&g_Ahi[row * KCAT + c4] = make_uint2(h0, h1);
    *(uint2*)&g_Alo[row * KCAT + c4] = make_uint2(l0, l1);
}

// ---------------- LSTM pointwise + output projection -----------------------------
__global__ void k_lstm(const float* __restrict__ bg, const float* __restrict__ cb,
                       const float* __restrict__ c0,
                       const float* __restrict__ fc_w, const float* __restrict__ fc_b,
                       float* __restrict__ dout, int out_size) {
    __shared__ float red[4];
    int n = blockIdx.x;
    int o = threadIdx.x;
    const float* a = &g_acc2[(size_t)n * KCAT];
    float p0 = a[0 * H2 + o] + bg[0 * H2 + o] + cb[0 * H2 + o];
    float p1 = a[1 * H2 + o] + bg[1 * H2 + o] + cb[1 * H2 + o];
    float p2 = a[2 * H2 + o] + bg[2 * H2 + o] + cb[2 * H2 + o];
    float p3 = a[3 * H2 + o] + bg[3 * H2 + o] + cb[3 * H2 + o];
    float ig = sigmoidf_(p0);
    float fg = sigmoidf_(p1);
    float tg = tanhf(p2);
    float og = sigmoidf_(p3);
    float cn = fg * c0[n * H2 + o] + ig * tg;
    float hn = og * tanhf(cn);
    int hidx = NREAL + n * H2 + o;
    if (hidx < out_size) dout[hidx] = hn;

    float r = fmaxf(hn, 0.f) * fc_w[o];
    #pragma unroll
    for (int d = 16; d > 0; d >>= 1) r += __shfl_down_sync(0xffffffffu, r, d);
    int lane = o & 31, warp = o >> 5;
    if (lane == 0) red[warp] = r;
    __syncthreads();
    if (o == 0 && n < NREAL) {
        float s = red[0] + red[1] + red[2] + red[3] + fc_b[0];
        dout[n] = s;
    }
}

// ---------------- launch -----------------------------------------------------------
extern "C" void kernel_launch(void* const* d_in, const int* in_sizes, int n_in,
                              void* d_out, int out_size) {
    const float *x = nullptr, *ew = nullptr, *h0 = nullptr, *c0 = nullptr;
    const float *fc0w = nullptr, *fc0b = nullptr, *Wx = nullptr, *bg = nullptr;
    const float *cw0 = nullptr, *cw1 = nullptr, *cb = nullptr;
    const float *fcw = nullptr, *fcb = nullptr;
    const void* ei = nullptr;

    int pos384[2] = {-1, -1};
    int i256 = -1, iBigW = -1;

    for (int i = 0; i < n_in; i++) {
        int s = in_sizes[i];
        const void* p = d_in[i];
        if (s == NREAL * FIN)      x = (const float*)p;
        else if (s == 2 * NE)      ei = p;
        else if (s == NE)          ew = (const float*)p;
        else if (s == NPADN * H2)  { if (pos384[0] < 0) pos384[0] = i; else pos384[1] = i; }
        else if (s == FIN * H1)    { fc0w = (const float*)p; iBigW = i; }
        else if (s == H1)          { fc0b = (const float*)p; i256 = i; }
        else if (s == 4 * H1 * H2) Wx = (const float*)p;
        else if (s == 4 * H2)      { if (!bg) bg = (const float*)p; else cb = (const float*)p; }
        else if (s == 4 * H2 * H2) { if (!cw0) cw0 = (const float*)p; else cw1 = (const float*)p; }
        else if (s == H2)          fcw = (const float*)p;
        else if (s == 1)           fcb = (const float*)p;
    }

    bool sorted_order = (i256 >= 0 && iBigW >= 0 && i256 < iBigW);
    if (sorted_order) {
        c0 = (const float*)d_in[pos384[0]];
        h0 = (const float*)d_in[pos384[1]];
    } else {
        h0 = (const float*)d_in[pos384[0]];
        c0 = (const float*)d_in[pos384[1]];
    }

    float* out = (float*)d_out;

    cudaFuncSetAttribute(k_gemm<0>, cudaFuncAttributeMaxDynamicSharedMemorySize, SMEMSZ);
    cudaFuncSetAttribute(k_gemm<1>, cudaFuncAttributeMaxDynamicSharedMemorySize, SMEMSZ);

    // k_gemm<0> kept at launch index 3 for the ncu profile slot
    k_probe_zero<<<(NPADN + 255) / 256, 256>>>(ei);            // 0
    k_convW<<<dim3(FIN / 32, H1 / 32), 256>>>(fc0w);           // 1
    k_buildB<<<(KCAT * KCAT + 255) / 256, 256>>>(Wx, cw0, cw1);// 2
    k_gemm<0><<<dim3(24, 2, 3), 256, SMEMSZ>>>(x);             // 3  <- profiled
    k_edges1<<<(NE / 2 + 255) / 256, 256>>>(ei, ew);           // 4
    k_scan<<<1, 1024>>>();                                     // 5 (dinv fused)
    k_edges2<<<(NE + 255) / 256, 256>>>(ei, ew);               // 6
    k_T1<<<NPADN, H2>>>(h0);                                   // 7
    k_epi1<<<(NPADN * H1 / 4 + 255) / 256, 256>>>(fc0b);       // 8
    k_gemm<1><<<dim3(24, 4, 1), 256, SMEMSZ>>>(nullptr);       // 9
    k_lstm<<<NPADN, H2>>>(bg, cb, c0, fcw, fcb, out, out_size);// 10
}

// round 12
// speedup vs baseline: 2.8626x; 1.0922x over previous
#include <cuda_runtime.h>
#include <cuda_bf16.h>
#include <cstdint>

#define NREAL 2800
#define NPADN 3000
#define MPAD  3072
#define FIN   8192
#define H1    256
#define H2    128
#define NE    179200
#define KCAT  512

// ---- shared GEMM constants ----
#define RSTR  20                    // words per smem row (conflict-free pad)
// GEMM2 (256 thr): 4 planes of 128 rows
#define PLANE (128 * RSTR)
#define SMEMSZ (2 * 4 * PLANE * 4)  // 80KB
// GEMM1 (512 thr): A planes 128 rows, B planes 256 rows
#define APLANE (128 * RSTR)         // 2560 words
#define BPLANE (256 * RSTR)         // 5120 words
#define WSTAGE (2 * APLANE + 2 * BPLANE)   // 15360 words = 60KB
#define SMEM1  (2 * WSTAGE * 4)     // 120KB

// ---------------- scratch (device-code references only!) --------------------
__device__ __align__(16) float g_part1[6 * MPAD * H1];
__device__ __align__(16) float g_acc2[MPAD * KCAT];
__device__ __align__(16) __nv_bfloat16 g_wThi[H1 * FIN];
__device__ __align__(16) __nv_bfloat16 g_wTlo[H1 * FIN];
__device__ __align__(16) __nv_bfloat16 g_Ahi[NPADN * KCAT];
__device__ __align__(16) __nv_bfloat16 g_Alo[NPADN * KCAT];
__device__ __align__(16) __nv_bfloat16 g_BThi[KCAT * KCAT];
__device__ __align__(16) __nv_bfloat16 g_BTlo[KCAT * KCAT];
__device__ __align__(16) float g_deg[NPADN];
__device__ __align__(16) float g_dinv[NPADN];
__device__ __align__(16) float g_wedge[NE];
__device__ __align__(16) int   g_cnt[NPADN];
__device__ __align__(16) int   g_cur[NPADN];
__device__ __align__(16) int   g_off[NPADN + 4];
__device__ __align__(16) int   g_bucket[NE];
__device__ int g_is32;

// ---------------- helpers ----------------------------------------------------
__device__ __forceinline__ float sigmoidf_(float x) { return 1.0f / (1.0f + expf(-x)); }

__device__ __forceinline__ void split2(float v, __nv_bfloat16& h, __nv_bfloat16& l) {
    h = __float2bfloat16_rn(v);
    l = __float2bfloat16_rn(v - __bfloat162float(h));
}
__device__ __forceinline__ void split2x2(float a, float b, uint32_t& h2, uint32_t& l2) {
    __nv_bfloat16 ha, la, hb, lb;
    split2(a, ha, la); split2(b, hb, lb);
    __nv_bfloat162 h = __halves2bfloat162(ha, hb);
    __nv_bfloat162 l = __halves2bfloat162(la, lb);
    h2 = *(uint32_t*)&h; l2 = *(uint32_t*)&l;
}
__device__ __forceinline__ int load_idx(const void* ei, int i) {
    if (g_is32) return ((const int*)ei)[i];
    return (int)((const long long*)ei)[i];
}
__device__ __forceinline__ void mma_bf16(float* d, const uint32_t* a,
                                         uint32_t b0, uint32_t b1) {
    asm volatile(
        "mma.sync.aligned.m16n8k16.row.col.f32.bf16.bf16.f32 "
        "{%0,%1,%2,%3}, {%4,%5,%6,%7}, {%8,%9}, {%0,%1,%2,%3};"
        : "+f"(d[0]), "+f"(d[1]), "+f"(d[2]), "+f"(d[3])
        : "r"(a[0]), "r"(a[1]), "r"(a[2]), "r"(a[3]), "r"(b0), "r"(b1));
}
#define LDMX4(r0, r1, r2, r3, a) \
    asm volatile("ldmatrix.sync.aligned.m8n8.x4.shared.b16 {%0,%1,%2,%3}, [%4];" \
                 : "=r"(r0), "=r"(r1), "=r"(r2), "=r"(r3) : "r"(a))
#define CPA16(dst, src, sz) \
    asm volatile("cp.async.ca.shared.global [%0], [%1], 16, %2;" \
                 :: "r"(dst), "l"(src), "r"(sz))
#define CPA_COMMIT() asm volatile("cp.async.commit_group;")
#define CPA_WAIT0()  asm volatile("cp.async.wait_group 0;")

// ---------------- probe + zero (fused) -----------------------------------------
__global__ void k_probe_zero(const void* p) {
    int i = blockIdx.x * blockDim.x + threadIdx.x;
    if (i < NPADN) { g_deg[i] = 0.f; g_cnt[i] = 0; g_cur[i] = 0; }
    if (blockIdx.x == 0) {
        __shared__ int any;
        if (threadIdx.x == 0) any = 0;
        __syncthreads();
        const int* q = (const int*)p;
        int v = 0;
        for (int j = threadIdx.x; j < 4096; j += blockDim.x) v |= q[2 * j + 1];
        if (v) atomicOr(&any, 1);
        __syncthreads();
        if (threadIdx.x == 0) g_is32 = (any != 0) ? 1 : 0;
    }
}

// fc0_w [FIN][H1] -> wT hi/lo [H1][FIN]
__global__ void k_convW(const float* __restrict__ w) {
    __shared__ float tile[32][33];
    int kb = blockIdx.x * 32, jb = blockIdx.y * 32;
    int tx = threadIdx.x & 31, ty = threadIdx.x >> 5;
    #pragma unroll
    for (int r = 0; r < 32; r += 8)
        tile[ty + r][tx] = w[(size_t)(kb + ty + r) * H1 + jb + tx];
    __syncthreads();
    #pragma unroll
    for (int r = 0; r < 32; r += 8) {
        float v = tile[tx][ty + r];
        __nv_bfloat16 h, l; split2(v, h, l);
        size_t o = (size_t)(jb + ty + r) * FIN + kb + tx;
        g_wThi[o] = h; g_wTlo[o] = l;
    }
}

// ---------------- graph preprocessing ------------------------------------------
__global__ void k_edges1(const void* __restrict__ ei,
                         const float* __restrict__ ew) {
    int base = (blockIdx.x * blockDim.x + threadIdx.x) * 2;
    #pragma unroll
    for (int j = 0; j < 2; j++) {
        int e = base + j;
        if (e < NE) {
            int r = load_idx(ei, e);
            int c = load_idx(ei, NE + e);
            if ((unsigned)r < NPADN) atomicAdd(&g_deg[r], ew[e]);
            if ((unsigned)c < NPADN) atomicAdd(&g_cnt[c], 1);
        }
    }
}

__global__ void k_scan() {
    int t = threadIdx.x;
    for (int i = t; i < NPADN; i += 1024) {
        float d = g_deg[i];
        g_dinv[i] = (d > 0.f) ? rsqrtf(d) : 0.f;
    }
    __shared__ int warp_sums[32];
    int i0 = t * 3;
    int v0 = (i0     < NPADN) ? g_cnt[i0]     : 0;
    int v1 = (i0 + 1 < NPADN) ? g_cnt[i0 + 1] : 0;
    int v2 = (i0 + 2 < NPADN) ? g_cnt[i0 + 2] : 0;
    int s = v0 + v1 + v2;
    int lane = t & 31, warp = t >> 5;
    int x = s;
    #pragma unroll
    for (int d = 1; d < 32; d <<= 1) {
        int y = __shfl_up_sync(0xffffffffu, x, d);
        if (lane >= d) x += y;
    }
    if (lane == 31) warp_sums[warp] = x;
    __syncthreads();
    if (warp == 0) {
        int w = warp_sums[lane];
        #pragma unroll
        for (int d = 1; d < 32; d <<= 1) {
            int y = __shfl_up_sync(0xffffffffu, w, d);
            if (lane >= d) w += y;
        }
        warp_sums[lane] = w;
    }
    __syncthreads();
    int base = (x - s) + (warp > 0 ? warp_sums[warp - 1] : 0);
    if (i0     < NPADN) g_off[i0]     = base;
    if (i0 + 1 < NPADN) g_off[i0 + 1] = base + v0;
    if (i0 + 2 < NPADN) g_off[i0 + 2] = base + v0 + v1;
    if (t == 1023) g_off[NPADN] = warp_sums[31];
}

__global__ void k_edges2(const void* __restrict__ ei,
                         const float* __restrict__ ew) {
    int e = blockIdx.x * blockDim.x + threadIdx.x;
    if (e < NE) {
        int c = load_idx(ei, NE + e);
        int r = load_idx(ei, e);
        if ((unsigned)c < NPADN && (unsigned)r < NPADN) {
            int pos = g_off[c] + atomicAdd(&g_cur[c], 1);
            if ((unsigned)pos < NE) {
                g_bucket[pos] = r;
                g_wedge[pos]  = -g_dinv[r] * ew[e] * g_dinv[c];
            }
        }
    }
}

__global__ void k_T1(const float* __restrict__ h0) {
    int c = blockIdx.x;
    int d = threadIdx.x;
    float acc = 0.f;
    int p0 = g_off[c], p1 = g_off[c + 1];
    for (int p = p0; p < p1; p++)
        acc = fmaf(g_wedge[p], h0[g_bucket[p] * H2 + d], acc);
    __nv_bfloat16 h, l;
    split2(h0[c * H2 + d], h, l);
    g_Ahi[c * KCAT + H1 + d] = h;
    g_Alo[c * KCAT + H1 + d] = l;
    split2(acc, h, l);
    g_Ahi[c * KCAT + H1 + H2 + d] = h;
    g_Alo[c * KCAT + H1 + H2 + d] = l;
}

__global__ void k_buildB(const float* __restrict__ Wx,
                         const float* __restrict__ cw0,
                         const float* __restrict__ cw1) {
    int idx = blockIdx.x * blockDim.x + threadIdx.x;
    if (idx >= KCAT * KCAT) return;
    int j = idx >> 9;
    int k = idx & 511;
    int gg = j >> 7;
    int o  = j & 127;
    float v;
    if (k < H1)            v = Wx [gg * H1 * H2 + k * H2 + o];
    else if (k < H1 + H2)  v = cw0[gg * H2 * H2 + (k - H1) * H2 + o];
    else                   v = cw1[gg * H2 * H2 + (k - H1 - H2) * H2 + o];
    __nv_bfloat16 h, l; split2(v, h, l);
    g_BThi[idx] = h;
    g_BTlo[idx] = l;
}

// ================= GEMM1: mma.sync bf16 3-pass, 512 threads =====================
// CTA tile 128x256 (full N), 16 warps 4x4, warp tile 32x64, BK=32,
// double-buffered cp.async(B) + reg-prefetch fp32 x (split in-kernel).
// Pass-major compute (hh, hl, lh) to keep regs <= 128.
__global__ void __launch_bounds__(512, 1) k_gemm1(const float* __restrict__ Xf) {
    extern __shared__ uint32_t smem[];
    uint32_t sbase = (uint32_t)__cvta_generic_to_shared(smem);

    int tid  = threadIdx.x;
    int warp = tid >> 5, lane = tid & 31;
    int wm = warp >> 2, wn = warp & 3;        // 4x4 warp grid
    int g  = lane >> 2, t4 = lane & 3;
    int m0 = blockIdx.x * 128;
    int z  = blockIdx.y;
    int koff  = (z < 4) ? z * 1344 : 5376 + (z - 4) * 1408;
    int iters = ((z < 4) ? 1344 : 1408) / 32;

    float acc[2][8][4];
    #pragma unroll
    for (int a = 0; a < 2; a++)
        #pragma unroll
        for (int b = 0; b < 8; b++)
            #pragma unroll
            for (int c = 0; c < 4; c++) acc[a][b][c] = 0.f;

    // x loader: quarter-row per thread (8 floats)
    int arow = tid >> 2, aq = tid & 3;
    int xg = m0 + arow; bool xok = xg < NREAL;
    // B loader: one 64B row of one plane per thread
    int prow = tid & 255, ppl = (tid >> 8) & 1;

    int lrowA = (lane & 7) + ((lane >> 3) & 1) * 8;
    int lwrdA = (lane >> 4) * 4;
    int lrowB = (lane & 7) + (lane >> 4) * 8;
    int lwrdB = ((lane >> 3) & 1) * 4;

    float4 ra[2];
    const float4* X4 = (const float4*)Xf;

    auto issue_loads = [&](int it, int st) {
        int k0 = koff + it * 32;
        const __nv_bfloat16* src = (ppl ? g_wTlo : g_wThi) + (size_t)prow * FIN + k0;
        uint32_t dst = sbase + (st * WSTAGE + 2 * APLANE + ppl * BPLANE + prow * RSTR) * 4;
        #pragma unroll
        for (int j = 0; j < 4; j++) CPA16(dst + j * 16, (const char*)src + j * 16, 16u);
        CPA_COMMIT();
        if (xok) {
            size_t b = (size_t)xg * (FIN / 4) + (k0 >> 2) + aq * 2;
            ra[0] = X4[b]; ra[1] = X4[b + 1];
        } else {
            ra[0] = make_float4(0.f, 0.f, 0.f, 0.f);
            ra[1] = make_float4(0.f, 0.f, 0.f, 0.f);
        }
    };

    auto split_sts = [&](int st) {
        uint32_t hw[4], lw[4];
        split2x2(ra[0].x, ra[0].y, hw[0], lw[0]);
        split2x2(ra[0].z, ra[0].w, hw[1], lw[1]);
        split2x2(ra[1].x, ra[1].y, hw[2], lw[2]);
        split2x2(ra[1].z, ra[1].w, hw[3], lw[3]);
        uint32_t* dh = smem + st * WSTAGE + arow * RSTR + aq * 4;
        *(uint4*)dh            = make_uint4(hw[0], hw[1], hw[2], hw[3]);
        *(uint4*)(dh + APLANE) = make_uint4(lw[0], lw[1], lw[2], lw[3]);
    };

    auto compute = [&](int st) {
        uint32_t base = (uint32_t)(st * WSTAGE);
        #pragma unroll
        for (int ks = 0; ks < 2; ks++) {
            uint32_t af[2][4];
            // ---- A hi fragments ----
            #pragma unroll
            for (int mt = 0; mt < 2; mt++) {
                int r = wm * 32 + mt * 16 + lrowA;
                uint32_t a = sbase + (base + r * RSTR + ks * 8 + lwrdA) * 4;
                LDMX4(af[mt][0], af[mt][1], af[mt][2], af[mt][3], a);
            }
            // ---- pass 1: hi x hi ----
            #pragma unroll
            for (int np = 0; np < 4; np++) {
                int r = wn * 64 + np * 16 + lrowB;
                uint32_t a = sbase + (base + 2 * APLANE + r * RSTR + ks * 8 + lwrdB) * 4;
                uint32_t b0, b1, b2, b3;
                LDMX4(b0, b1, b2, b3, a);
                #pragma unroll
                for (int mt = 0; mt < 2; mt++) {
                    mma_bf16(acc[mt][2 * np],     af[mt], b0, b1);
                    mma_bf16(acc[mt][2 * np + 1], af[mt], b2, b3);
                }
            }
            // ---- pass 2: hi x lo ----
            #pragma unroll
            for (int np = 0; np < 4; np++) {
                int r = wn * 64 + np * 16 + lrowB;
                uint32_t a = sbase + (base + 2 * APLANE + BPLANE + r * RSTR + ks * 8 + lwrdB) * 4;
                uint32_t b0, b1, b2, b3;
                LDMX4(b0, b1, b2, b3, a);
                #pragma unroll
                for (int mt = 0; mt < 2; mt++) {
                    mma_bf16(acc[mt][2 * np],     af[mt], b0, b1);
                    mma_bf16(acc[mt][2 * np + 1], af[mt], b2, b3);
                }
            }
            // ---- A lo fragments (overwrite) ----
            #pragma unroll
            for (int mt = 0; mt < 2; mt++) {
                int r = wm * 32 + mt * 16 + lrowA;
                uint32_t a = sbase + (base + APLANE + r * RSTR + ks * 8 + lwrdA) * 4;
                LDMX4(af[mt][0], af[mt][1], af[mt][2], af[mt][3], a);
            }
            // ---- pass 3: lo x hi ----
            #pragma unroll
            for (int np = 0; np < 4; np++) {
                int r = wn * 64 + np * 16 + lrowB;
                uint32_t a = sbase + (base + 2 * APLANE + r * RSTR + ks * 8 + lwrdB) * 4;
                uint32_t b0, b1, b2, b3;
                LDMX4(b0, b1, b2, b3, a);
                #pragma unroll
                for (int mt = 0; mt < 2; mt++) {
                    mma_bf16(acc[mt][2 * np],     af[mt], b0, b1);
                    mma_bf16(acc[mt][2 * np + 1], af[mt], b2, b3);
                }
            }
        }
    };

    issue_loads(0, 0);
    split_sts(0);
    CPA_WAIT0();
    __syncthreads();

    for (int it = 0; it < iters; it++) {
        int cur = it & 1;
        if (it + 1 < iters) issue_loads(it + 1, cur ^ 1);
        compute(cur);
        if (it + 1 < iters) split_sts(cur ^ 1);
        CPA_WAIT0();
        __syncthreads();
    }

    float* C = g_part1 + (size_t)z * (MPAD * H1);
    #pragma unroll
    for (int mt = 0; mt < 2; mt++)
        #pragma unroll
        for (int nt = 0; nt < 8; nt++) {
            int r0 = m0 + wm * 32 + mt * 16 + g;
            int cc = wn * 64 + nt * 8 + t4 * 2;
            *(float2*)&C[(size_t)r0 * H1 + cc]       = make_float2(acc[mt][nt][0], acc[mt][nt][1]);
            *(float2*)&C[(size_t)(r0 + 8) * H1 + cc] = make_float2(acc[mt][nt][2], acc[mt][nt][3]);
        }
}

// ================= GEMM2: mma.sync bf16 3-pass, 256 threads (R10) ==============
__global__ void __launch_bounds__(256, 1) k_gemm2() {
    constexpr int K  = KCAT;
    constexpr int N  = KCAT;
    constexpr int MR = NPADN;

    extern __shared__ uint32_t smem[];
    uint32_t sbase = (uint32_t)__cvta_generic_to_shared(smem);

    int tid  = threadIdx.x;
    int warp = tid >> 5, lane = tid & 31;
    int wm = warp >> 1, wn = warp & 1;
    int g  = lane >> 2, t4 = lane & 3;
    int m0 = blockIdx.x * 128;
    int n0 = blockIdx.y * 128;
    int iters = K / 32;

    float acc[2][8][4];
    #pragma unroll
    for (int a = 0; a < 2; a++)
        #pragma unroll
        for (int b = 0; b < 8; b++)
            #pragma unroll
            for (int c = 0; c < 4; c++) acc[a][b][c] = 0.f;

    int prow  = tid & 127, ppl = tid >> 7;
    int ag    = m0 + prow;  bool aok = ag < MR;
    unsigned asz = aok ? 16u : 0u;

    int lrowA = (lane & 7) + ((lane >> 3) & 1) * 8;
    int lwrdA = (lane >> 4) * 4;
    int lrowB = (lane & 7) + (lane >> 4) * 8;
    int lwrdB = ((lane >> 3) & 1) * 4;

    auto issue_loads = [&](int it, int st) {
        int k0 = it * 32;
        {
            const __nv_bfloat16* src = (ppl ? g_BTlo : g_BThi) + (size_t)(n0 + prow) * K + k0;
            uint32_t dst = sbase + ((st * 4 + 2 + ppl) * PLANE + prow * RSTR) * 4;
            #pragma unroll
            for (int j = 0; j < 4; j++) CPA16(dst + j * 16, (const char*)src + j * 16, 16u);
        }
        {
            const __nv_bfloat16* src = (ppl ? g_Alo : g_Ahi) + (size_t)ag * K + k0;
            uint32_t dst = sbase + ((st * 4 + ppl) * PLANE + prow * RSTR) * 4;
            #pragma unroll
            for (int j = 0; j < 4; j++) CPA16(dst + j * 16, (const char*)src + j * 16, asz);
        }
        CPA_COMMIT();
    };

    auto compute = [&](int st) {
        #pragma unroll
        for (int ks = 0; ks < 2; ks++) {
            uint32_t ah[2][4], al[2][4];
            #pragma unroll
            for (int mt = 0; mt < 2; mt++) {
                int r = wm * 32 + mt * 16 + lrowA;
                uint32_t oh = sbase + ((st * 4 + 0) * PLANE + r * RSTR + ks * 8 + lwrdA) * 4;
                uint32_t ol = sbase + ((st * 4 + 1) * PLANE + r * RSTR + ks * 8 + lwrdA) * 4;
                LDMX4(ah[mt][0], ah[mt][1], ah[mt][2], ah[mt][3], oh);
                LDMX4(al[mt][0], al[mt][1], al[mt][2], al[mt][3], ol);
            }
            #pragma unroll
            for (int np = 0; np < 4; np++) {
                int r = wn * 64 + np * 16 + lrowB;
                uint32_t oh = sbase + ((st * 4 + 2) * PLANE + r * RSTR + ks * 8 + lwrdB) * 4;
                uint32_t ol = sbase + ((st * 4 + 3) * PLANE + r * RSTR + ks * 8 + lwrdB) * 4;
                uint32_t bh0, bh1, bh2, bh3, bl0, bl1, bl2, bl3;
                LDMX4(bh0, bh1, bh2, bh3, oh);
                LDMX4(bl0, bl1, bl2, bl3, ol);
                #pragma unroll
                for (int mt = 0; mt < 2; mt++) {
                    mma_bf16(acc[mt][2 * np],     ah[mt], bh0, bh1);
                    mma_bf16(acc[mt][2 * np],     ah[mt], bl0, bl1);
                    mma_bf16(acc[mt][2 * np],     al[mt], bh0, bh1);
                    mma_bf16(acc[mt][2 * np + 1], ah[mt], bh2, bh3);
                    mma_bf16(acc[mt][2 * np + 1], ah[mt], bl2, bl3);
                    mma_bf16(acc[mt][2 * np + 1], al[mt], bh2, bh3);
                }
            }
        }
    };

    issue_loads(0, 0);
    CPA_WAIT0();
    __syncthreads();

    for (int it = 0; it < iters; it++) {
        int cur = it & 1;
        if (it + 1 < iters) issue_loads(it + 1, cur ^ 1);
        compute(cur);
        CPA_WAIT0();
        __syncthreads();
    }

    float* C = g_acc2;
    #pragma unroll
    for (int mt = 0; mt < 2; mt++)
        #pragma unroll
        for (int nt = 0; nt < 8; nt++) {
            int r0 = m0 + wm * 32 + mt * 16 + g;
            int cc = n0 + wn * 64 + nt * 8 + t4 * 2;
            *(float2*)&C[(size_t)r0 * N + cc]       = make_float2(acc[mt][nt][0], acc[mt][nt][1]);
            *(float2*)&C[(size_t)(r0 + 8) * N + cc] = make_float2(acc[mt][nt][2], acc[mt][nt][3]);
        }
}

// ---------------- epilogue 1: reduce 6 partials + bias + relu + split ------------
__global__ void k_epi1(const float* __restrict__ fc0_b) {
    int idx = blockIdx.x * blockDim.x + threadIdx.x;
    if (idx >= NPADN * H1 / 4) return;
    int row = idx >> 6;
    int c4  = (idx & 63) * 4;
    float4 s = make_float4(0.f, 0.f, 0.f, 0.f);
    #pragma unroll
    for (int z = 0; z < 6; z++) {
        float4 p = *(const float4*)&g_part1[(size_t)z * MPAD * H1 + row * H1 + c4];
        s.x += p.x; s.y += p.y; s.z += p.z; s.w += p.w;
    }
    float4 b = *(const float4*)&fc0_b[c4];
    float z0 = fmaxf(s.x + b.x, 0.f), z1 = fmaxf(s.y + b.y, 0.f);
    float z2 = fmaxf(s.z + b.z, 0.f), z3 = fmaxf(s.w + b.w, 0.f);
    uint32_t h0, l0, h1, l1;
    split2x2(z0, z1, h0, l0);
    split2x2(z2, z3, h1, l1);
    *(uint2*)&g_Ahi[row * KCAT + c4] = make_uint2(h0, h1);
    *(uint2*)&g_Alo[row * KCAT + c4] = make_uint2(l0, l1);
}

// ---------------- LSTM pointwise + output projection -----------------------------
__global__ void k_lstm(const float* __restrict__ bg, const float* __restrict__ cb,
                       const float* __restrict__ c0,
                       const float* __restrict__ fc_w, const float* __restrict__ fc_b,
                       float* __restrict__ dout, int out_size) {
    __shared__ float red[4];
    int n = blockIdx.x;
    int o = threadIdx.x;
    const float* a = &g_acc2[(size_t)n * KCAT];
    float p0 = a[0 * H2 + o] + bg[0 * H2 + o] + cb[0 * H2 + o];
    float p1 = a[1 * H2 + o] + bg[1 * H2 + o] + cb[1 * H2 + o];
    float p2 = a[2 * H2 + o] + bg[2 * H2 + o] + cb[2 * H2 + o];
    float p3 = a[3 * H2 + o] + bg[3 * H2 + o] + cb[3 * H2 + o];
    float ig = sigmoidf_(p0);
    float fg = sigmoidf_(p1);
    float tg = tanhf(p2);
    float og = sigmoidf_(p3);
    float cn = fg * c0[n * H2 + o] + ig * tg;
    float hn = og * tanhf(cn);
    int hidx = NREAL + n * H2 + o;
    if (hidx < out_size) dout[hidx] = hn;

    float r = fmaxf(hn, 0.f) * fc_w[o];
    #pragma unroll
    for (int d = 16; d > 0; d >>= 1) r += __shfl_down_sync(0xffffffffu, r, d);
    int lane = o & 31, warp = o >> 5;
    if (lane == 0) red[warp] = r;
    __syncthreads();
    if (o == 0 && n < NREAL) {
        float s = red[0] + red[1] + red[2] + red[3] + fc_b[0];
        dout[n] = s;
    }
}

// ---------------- launch -----------------------------------------------------------
extern "C" void kernel_launch(void* const* d_in, const int* in_sizes, int n_in,
                              void* d_out, int out_size) {
    const float *x = nullptr, *ew = nullptr, *h0 = nullptr, *c0 = nullptr;
    const float *fc0w = nullptr, *fc0b = nullptr, *Wx = nullptr, *bg = nullptr;
    const float *cw0 = nullptr, *cw1 = nullptr, *cb = nullptr;
    const float *fcw = nullptr, *fcb = nullptr;
    const void* ei = nullptr;

    int pos384[2] = {-1, -1};
    int i256 = -1, iBigW = -1;

    for (int i = 0; i < n_in; i++) {
        int s = in_sizes[i];
        const void* p = d_in[i];
        if (s == NREAL * FIN)      x = (const float*)p;
        else if (s == 2 * NE)      ei = p;
        else if (s == NE)          ew = (const float*)p;
        else if (s == NPADN * H2)  { if (pos384[0] < 0) pos384[0] = i; else pos384[1] = i; }
        else if (s == FIN * H1)    { fc0w = (const float*)p; iBigW = i; }
        else if (s == H1)          { fc0b = (const float*)p; i256 = i; }
        else if (s == 4 * H1 * H2) Wx = (const float*)p;
        else if (s == 4 * H2)      { if (!bg) bg = (const float*)p; else cb = (const float*)p; }
        else if (s == 4 * H2 * H2) { if (!cw0) cw0 = (const float*)p; else cw1 = (const float*)p; }
        else if (s == H2)          fcw = (const float*)p;
        else if (s == 1)           fcb = (const float*)p;
    }

    bool sorted_order = (i256 >= 0 && iBigW >= 0 && i256 < iBigW);
    if (sorted_order) {
        c0 = (const float*)d_in[pos384[0]];
        h0 = (const float*)d_in[pos384[1]];
    } else {
        h0 = (const float*)d_in[pos384[0]];
        c0 = (const float*)d_in[pos384[1]];
    }

    float* out = (float*)d_out;

    cudaFuncSetAttribute(k_gemm1, cudaFuncAttributeMaxDynamicSharedMemorySize, SMEM1);
    cudaFuncSetAttribute(k_gemm2, cudaFuncAttributeMaxDynamicSharedMemorySize, SMEMSZ);

    // k_gemm1 at launch index 3 (ncu profile slot)
    k_probe_zero<<<(NPADN + 255) / 256, 256>>>(ei);            // 0
    k_convW<<<dim3(FIN / 32, H1 / 32), 256>>>(fc0w);           // 1
    k_buildB<<<(KCAT * KCAT + 255) / 256, 256>>>(Wx, cw0, cw1);// 2
    k_gemm1<<<dim3(24, 6), 512, SMEM1>>>(x);                   // 3  <- profiled
    k_edges1<<<(NE / 2 + 255) / 256, 256>>>(ei, ew);           // 4
    k_scan<<<1, 1024>>>();                                     // 5
    k_edges2<<<(NE + 255) / 256, 256>>>(ei, ew);               // 6
    k_T1<<<NPADN, H2>>>(h0);                                   // 7
    k_epi1<<<(NPADN * H1 / 4 + 255) / 256, 256>>>(fc0b);       // 8
    k_gemm2<<<dim3(24, 4), 256, SMEMSZ>>>();                   // 9
    k_lstm<<<NPADN, H2>>>(bg, cb, c0, fcw, fcb, out, out_size);// 10
}

// round 13
// speedup vs baseline: 2.8894x; 1.0094x over previous
#include <cuda_runtime.h>
#include <cuda_bf16.h>
#include <cstdint>

#define NREAL 2800
#define NPADN 3000
#define MPAD  3072
#define FIN   8192
#define H1    256
#define H2    128
#define NE    179200
#define KCAT  512

// ---- shared GEMM constants ----
#define RSTR  20                    // words per smem row (conflict-free pad)
#define PLANE (128 * RSTR)
#define SMEMSZ (2 * 4 * PLANE * 4)  // 80KB (GEMM2)
#define APLANE (128 * RSTR)         // 2560 words
#define BPLANE (256 * RSTR)         // 5120 words
#define WSTAGE (2 * APLANE + 2 * BPLANE)   // 15360 words = 60KB
#define SMEM1  (2 * WSTAGE * 4)     // 120KB (GEMM1)

// ---------------- scratch (device-code references only!) --------------------
__device__ __align__(16) float g_part1[6 * MPAD * H1];
__device__ __align__(16) float g_acc2[MPAD * KCAT];
__device__ __align__(16) __nv_bfloat16 g_wThi[H1 * FIN];
__device__ __align__(16) __nv_bfloat16 g_wTlo[H1 * FIN];
__device__ __align__(16) __nv_bfloat16 g_Ahi[NPADN * KCAT];
__device__ __align__(16) __nv_bfloat16 g_Alo[NPADN * KCAT];
__device__ __align__(16) __nv_bfloat16 g_BThi[KCAT * KCAT];
__device__ __align__(16) __nv_bfloat16 g_BTlo[KCAT * KCAT];
__device__ __align__(16) float g_deg[NPADN];
__device__ __align__(16) float g_dinv[NPADN];
__device__ __align__(16) float g_wedge[NE];
__device__ __align__(16) int   g_cnt[NPADN];
__device__ __align__(16) int   g_cur[NPADN];
__device__ __align__(16) int   g_off[NPADN + 4];
__device__ __align__(16) int   g_bucket[NE];
__device__ int g_is32;

// ---------------- helpers ----------------------------------------------------
__device__ __forceinline__ float sigmoidf_(float x) { return 1.0f / (1.0f + expf(-x)); }

__device__ __forceinline__ void split2(float v, __nv_bfloat16& h, __nv_bfloat16& l) {
    h = __float2bfloat16_rn(v);
    l = __float2bfloat16_rn(v - __bfloat162float(h));
}
__device__ __forceinline__ void split2x2(float a, float b, uint32_t& h2, uint32_t& l2) {
    __nv_bfloat16 ha, la, hb, lb;
    split2(a, ha, la); split2(b, hb, lb);
    __nv_bfloat162 h = __halves2bfloat162(ha, hb);
    __nv_bfloat162 l = __halves2bfloat162(la, lb);
    h2 = *(uint32_t*)&h; l2 = *(uint32_t*)&l;
}
__device__ __forceinline__ int load_idx(const void* ei, int i) {
    if (g_is32) return ((const int*)ei)[i];
    return (int)((const long long*)ei)[i];
}
__device__ __forceinline__ void mma_bf16(float* d, const uint32_t* a,
                                         uint32_t b0, uint32_t b1) {
    asm volatile(
        "mma.sync.aligned.m16n8k16.row.col.f32.bf16.bf16.f32 "
        "{%0,%1,%2,%3}, {%4,%5,%6,%7}, {%8,%9}, {%0,%1,%2,%3};"
        : "+f"(d[0]), "+f"(d[1]), "+f"(d[2]), "+f"(d[3])
        : "r"(a[0]), "r"(a[1]), "r"(a[2]), "r"(a[3]), "r"(b0), "r"(b1));
}
#define LDMX4(r0, r1, r2, r3, a) \
    asm volatile("ldmatrix.sync.aligned.m8n8.x4.shared.b16 {%0,%1,%2,%3}, [%4];" \
                 : "=r"(r0), "=r"(r1), "=r"(r2), "=r"(r3) : "r"(a))
#define CPA16(dst, src, sz) \
    asm volatile("cp.async.ca.shared.global [%0], [%1], 16, %2;" \
                 :: "r"(dst), "l"(src), "r"(sz))
#define CPA_COMMIT() asm volatile("cp.async.commit_group;")
#define CPA_WAIT0()  asm volatile("cp.async.wait_group 0;")

// ---------------- probe + zero (fused) -----------------------------------------
__global__ void k_probe_zero(const void* p) {
    int i = blockIdx.x * blockDim.x + threadIdx.x;
    if (i < NPADN) { g_deg[i] = 0.f; g_cnt[i] = 0; g_cur[i] = 0; }
    if (blockIdx.x == 0) {
        __shared__ int any;
        if (threadIdx.x == 0) any = 0;
        __syncthreads();
        const int* q = (const int*)p;
        int v = 0;
        for (int j = threadIdx.x; j < 4096; j += blockDim.x) v |= q[2 * j + 1];
        if (v) atomicOr(&any, 1);
        __syncthreads();
        if (threadIdx.x == 0) g_is32 = (any != 0) ? 1 : 0;
    }
}

// fc0_w [FIN][H1] -> wT hi/lo [H1][FIN]
__global__ void k_convW(const float* __restrict__ w) {
    __shared__ float tile[32][33];
    int kb = blockIdx.x * 32, jb = blockIdx.y * 32;
    int tx = threadIdx.x & 31, ty = threadIdx.x >> 5;
    #pragma unroll
    for (int r = 0; r < 32; r += 8)
        tile[ty + r][tx] = w[(size_t)(kb + ty + r) * H1 + jb + tx];
    __syncthreads();
    #pragma unroll
    for (int r = 0; r < 32; r += 8) {
        float v = tile[tx][ty + r];
        __nv_bfloat16 h, l; split2(v, h, l);
        size_t o = (size_t)(jb + ty + r) * FIN + kb + tx;
        g_wThi[o] = h; g_wTlo[o] = l;
    }
}

// ---------------- graph preprocessing ------------------------------------------
__global__ void k_edges1(const void* __restrict__ ei,
                         const float* __restrict__ ew) {
    int base = (blockIdx.x * blockDim.x + threadIdx.x) * 2;
    #pragma unroll
    for (int j = 0; j < 2; j++) {
        int e = base + j;
        if (e < NE) {
            int r = load_idx(ei, e);
            int c = load_idx(ei, NE + e);
            if ((unsigned)r < NPADN) atomicAdd(&g_deg[r], ew[e]);
            if ((unsigned)c < NPADN) atomicAdd(&g_cnt[c], 1);
        }
    }
}

__global__ void k_scan() {
    int t = threadIdx.x;
    for (int i = t; i < NPADN; i += 1024) {
        float d = g_deg[i];
        g_dinv[i] = (d > 0.f) ? rsqrtf(d) : 0.f;
    }
    __shared__ int warp_sums[32];
    int i0 = t * 3;
    int v0 = (i0     < NPADN) ? g_cnt[i0]     : 0;
    int v1 = (i0 + 1 < NPADN) ? g_cnt[i0 + 1] : 0;
    int v2 = (i0 + 2 < NPADN) ? g_cnt[i0 + 2] : 0;
    int s = v0 + v1 + v2;
    int lane = t & 31, warp = t >> 5;
    int x = s;
    #pragma unroll
    for (int d = 1; d < 32; d <<= 1) {
        int y = __shfl_up_sync(0xffffffffu, x, d);
        if (lane >= d) x += y;
    }
    if (lane == 31) warp_sums[warp] = x;
    __syncthreads();
    if (warp == 0) {
        int w = warp_sums[lane];
        #pragma unroll
        for (int d = 1; d < 32; d <<= 1) {
            int y = __shfl_up_sync(0xffffffffu, w, d);
            if (lane >= d) w += y;
        }
        warp_sums[lane] = w;
    }
    __syncthreads();
    int base = (x - s) + (warp > 0 ? warp_sums[warp - 1] : 0);
    if (i0     < NPADN) g_off[i0]     = base;
    if (i0 + 1 < NPADN) g_off[i0 + 1] = base + v0;
    if (i0 + 2 < NPADN) g_off[i0 + 2] = base + v0 + v1;
    if (t == 1023) g_off[NPADN] = warp_sums[31];
}

__global__ void k_edges2(const void* __restrict__ ei,
                         const float* __restrict__ ew) {
    int e = blockIdx.x * blockDim.x + threadIdx.x;
    if (e < NE) {
        int c = load_idx(ei, NE + e);
        int r = load_idx(ei, e);
        if ((unsigned)c < NPADN && (unsigned)r < NPADN) {
            int pos = g_off[c] + atomicAdd(&g_cur[c], 1);
            if ((unsigned)pos < NE) {
                g_bucket[pos] = r;
                g_wedge[pos]  = -g_dinv[r] * ew[e] * g_dinv[c];
            }
        }
    }
}

__global__ void k_T1(const float* __restrict__ h0) {
    int c = blockIdx.x;
    int d = threadIdx.x;
    float acc = 0.f;
    int p0 = g_off[c], p1 = g_off[c + 1];
    for (int p = p0; p < p1; p++)
        acc = fmaf(g_wedge[p], h0[g_bucket[p] * H2 + d], acc);
    __nv_bfloat16 h, l;
    split2(h0[c * H2 + d], h, l);
    g_Ahi[c * KCAT + H1 + d] = h;
    g_Alo[c * KCAT + H1 + d] = l;
    split2(acc, h, l);
    g_Ahi[c * KCAT + H1 + H2 + d] = h;
    g_Alo[c * KCAT + H1 + H2 + d] = l;
}

__global__ void k_buildB(const float* __restrict__ Wx,
                         const float* __restrict__ cw0,
                         const float* __restrict__ cw1) {
    int idx = blockIdx.x * blockDim.x + threadIdx.x;
    if (idx >= KCAT * KCAT) return;
    int j = idx >> 9;
    int k = idx & 511;
    int gg = j >> 7;
    int o  = j & 127;
    float v;
    if (k < H1)            v = Wx [gg * H1 * H2 + k * H2 + o];
    else if (k < H1 + H2)  v = cw0[gg * H2 * H2 + (k - H1) * H2 + o];
    else                   v = cw1[gg * H2 * H2 + (k - H1 - H2) * H2 + o];
    __nv_bfloat16 h, l; split2(v, h, l);
    g_BThi[idx] = h;
    g_BTlo[idx] = l;
}

// ================= GEMM1: mma.sync bf16 3-pass, 512 threads =====================
// CTA tile 128x256, 16 warps 4x4, warp tile 32x64, BK=32. B-fragment-held
// schedule: per ks load A-hi + A-lo (4 LDMX4), then per n-tile load B-hi once
// (serves hh AND lh) then B-lo (hl): 12 LDMX4 / warp / ks.
__global__ void __launch_bounds__(512, 1) k_gemm1(const float* __restrict__ Xf) {
    extern __shared__ uint32_t smem[];
    uint32_t sbase = (uint32_t)__cvta_generic_to_shared(smem);

    int tid  = threadIdx.x;
    int warp = tid >> 5, lane = tid & 31;
    int wm = warp >> 2, wn = warp & 3;        // 4x4 warp grid
    int g  = lane >> 2, t4 = lane & 3;
    int m0 = blockIdx.x * 128;
    int z  = blockIdx.y;
    int koff  = (z < 4) ? z * 1344 : 5376 + (z - 4) * 1408;
    int iters = ((z < 4) ? 1344 : 1408) / 32;

    float acc[2][8][4];
    #pragma unroll
    for (int a = 0; a < 2; a++)
        #pragma unroll
        for (int b = 0; b < 8; b++)
            #pragma unroll
            for (int c = 0; c < 4; c++) acc[a][b][c] = 0.f;

    // x loader: quarter-row per thread (8 floats)
    int arow = tid >> 2, aq = tid & 3;
    int xg = m0 + arow; bool xok = xg < NREAL;
    // B loader: one 64B row of one plane per thread
    int prow = tid & 255, ppl = (tid >> 8) & 1;

    int lrowA = (lane & 7) + ((lane >> 3) & 1) * 8;
    int lwrdA = (lane >> 4) * 4;
    int lrowB = (lane & 7) + (lane >> 4) * 8;
    int lwrdB = ((lane >> 3) & 1) * 4;

    float4 ra[2];
    const float4* X4 = (const float4*)Xf;

    auto issue_loads = [&](int it, int st) {
        int k0 = koff + it * 32;
        const __nv_bfloat16* src = (ppl ? g_wTlo : g_wThi) + (size_t)prow * FIN + k0;
        uint32_t dst = sbase + (st * WSTAGE + 2 * APLANE + ppl * BPLANE + prow * RSTR) * 4;
        #pragma unroll
        for (int j = 0; j < 4; j++) CPA16(dst + j * 16, (const char*)src + j * 16, 16u);
        CPA_COMMIT();
        if (xok) {
            size_t b = (size_t)xg * (FIN / 4) + (k0 >> 2) + aq * 2;
            ra[0] = X4[b]; ra[1] = X4[b + 1];
        } else {
            ra[0] = make_float4(0.f, 0.f, 0.f, 0.f);
            ra[1] = make_float4(0.f, 0.f, 0.f, 0.f);
        }
    };

    auto split_sts = [&](int st) {
        uint32_t hw[4], lw[4];
        split2x2(ra[0].x, ra[0].y, hw[0], lw[0]);
        split2x2(ra[0].z, ra[0].w, hw[1], lw[1]);
        split2x2(ra[1].x, ra[1].y, hw[2], lw[2]);
        split2x2(ra[1].z, ra[1].w, hw[3], lw[3]);
        uint32_t* dh = smem + st * WSTAGE + arow * RSTR + aq * 4;
        *(uint4*)dh            = make_uint4(hw[0], hw[1], hw[2], hw[3]);
        *(uint4*)(dh + APLANE) = make_uint4(lw[0], lw[1], lw[2], lw[3]);
    };

    auto compute = [&](int st) {
        uint32_t base = (uint32_t)(st * WSTAGE);
        #pragma unroll
        for (int ks = 0; ks < 2; ks++) {
            uint32_t ah[2][4], al[2][4];
            #pragma unroll
            for (int mt = 0; mt < 2; mt++) {
                int r = wm * 32 + mt * 16 + lrowA;
                uint32_t oh = sbase + (base + r * RSTR + ks * 8 + lwrdA) * 4;
                uint32_t ol = sbase + (base + APLANE + r * RSTR + ks * 8 + lwrdA) * 4;
                LDMX4(ah[mt][0], ah[mt][1], ah[mt][2], ah[mt][3], oh);
                LDMX4(al[mt][0], al[mt][1], al[mt][2], al[mt][3], ol);
            }
            #pragma unroll
            for (int np = 0; np < 4; np++) {
                int r = wn * 64 + np * 16 + lrowB;
                uint32_t oh = sbase + (base + 2 * APLANE + r * RSTR + ks * 8 + lwrdB) * 4;
                uint32_t ol = sbase + (base + 2 * APLANE + BPLANE + r * RSTR + ks * 8 + lwrdB) * 4;
                uint32_t b0, b1, b2, b3;
                // B-hi: serves hh and lh passes
                LDMX4(b0, b1, b2, b3, oh);
                #pragma unroll
                for (int mt = 0; mt < 2; mt++) {
                    mma_bf16(acc[mt][2 * np],     ah[mt], b0, b1);
                    mma_bf16(acc[mt][2 * np + 1], ah[mt], b2, b3);
                    mma_bf16(acc[mt][2 * np],     al[mt], b0, b1);
                    mma_bf16(acc[mt][2 * np + 1], al[mt], b2, b3);
                }
                // B-lo: hl pass
                LDMX4(b0, b1, b2, b3, ol);
                #pragma unroll
                for (int mt = 0; mt < 2; mt++) {
                    mma_bf16(acc[mt][2 * np],     ah[mt], b0, b1);
                    mma_bf16(acc[mt][2 * np + 1], ah[mt], b2, b3);
                }
            }
        }
    };

    issue_loads(0, 0);
    split_sts(0);
    CPA_WAIT0();
    __syncthreads();

    for (int it = 0; it < iters; it++) {
        int cur = it & 1;
        if (it + 1 < iters) issue_loads(it + 1, cur ^ 1);
        compute(cur);
        if (it + 1 < iters) split_sts(cur ^ 1);
        CPA_WAIT0();
        __syncthreads();
    }

    float* C = g_part1 + (size_t)z * (MPAD * H1);
    #pragma unroll
    for (int mt = 0; mt < 2; mt++)
        #pragma unroll
        for (int nt = 0; nt < 8; nt++) {
            int r0 = m0 + wm * 32 + mt * 16 + g;
            int cc = wn * 64 + nt * 8 + t4 * 2;
            *(float2*)&C[(size_t)r0 * H1 + cc]       = make_float2(acc[mt][nt][0], acc[mt][nt][1]);
            *(float2*)&C[(size_t)(r0 + 8) * H1 + cc] = make_float2(acc[mt][nt][2], acc[mt][nt][3]);
        }
}

// ================= GEMM2: mma.sync bf16 3-pass, 256 threads ====================
__global__ void __launch_bounds__(256, 1) k_gemm2() {
    constexpr int K  = KCAT;
    constexpr int N  = KCAT;
    constexpr int MR = NPADN;

    extern __shared__ uint32_t smem[];
    uint32_t sbase = (uint32_t)__cvta_generic_to_shared(smem);

    int tid  = threadIdx.x;
    int warp = tid >> 5, lane = tid & 31;
    int wm = warp >> 1, wn = warp & 1;
    int g  = lane >> 2, t4 = lane & 3;
    int m0 = blockIdx.x * 128;
    int n0 = blockIdx.y * 128;
    int iters = K / 32;

    float acc[2][8][4];
    #pragma unroll
    for (int a = 0; a < 2; a++)
        #pragma unroll
        for (int b = 0; b < 8; b++)
            #pragma unroll
            for (int c = 0; c < 4; c++) acc[a][b][c] = 0.f;

    int prow  = tid & 127, ppl = tid >> 7;
    int ag    = m0 + prow;  bool aok = ag < MR;
    unsigned asz = aok ? 16u : 0u;

    int lrowA = (lane & 7) + ((lane >> 3) & 1) * 8;
    int lwrdA = (lane >> 4) * 4;
    int lrowB = (lane & 7) + (lane >> 4) * 8;
    int lwrdB = ((lane >> 3) & 1) * 4;

    auto issue_loads = [&](int it, int st) {
        int k0 = it * 32;
        {
            const __nv_bfloat16* src = (ppl ? g_BTlo : g_BThi) + (size_t)(n0 + prow) * K + k0;
            uint32_t dst = sbase + ((st * 4 + 2 + ppl) * PLANE + prow * RSTR) * 4;
            #pragma unroll
            for (int j = 0; j < 4; j++) CPA16(dst + j * 16, (const char*)src + j * 16, 16u);
        }
        {
            const __nv_bfloat16* src = (ppl ? g_Alo : g_Ahi) + (size_t)ag * K + k0;
            uint32_t dst = sbase + ((st * 4 + ppl) * PLANE + prow * RSTR) * 4;
            #pragma unroll
            for (int j = 0; j < 4; j++) CPA16(dst + j * 16, (const char*)src + j * 16, asz);
        }
        CPA_COMMIT();
    };

    auto compute = [&](int st) {
        #pragma unroll
        for (int ks = 0; ks < 2; ks++) {
            uint32_t ah[2][4], al[2][4];
            #pragma unroll
            for (int mt = 0; mt < 2; mt++) {
                int r = wm * 32 + mt * 16 + lrowA;
                uint32_t oh = sbase + ((st * 4 + 0) * PLANE + r * RSTR + ks * 8 + lwrdA) * 4;
                uint32_t ol = sbase + ((st * 4 + 1) * PLANE + r * RSTR + ks * 8 + lwrdA) * 4;
                LDMX4(ah[mt][0], ah[mt][1], ah[mt][2], ah[mt][3], oh);
                LDMX4(al[mt][0], al[mt][1], al[mt][2], al[mt][3], ol);
            }
            #pragma unroll
            for (int np = 0; np < 4; np++) {
                int r = wn * 64 + np * 16 + lrowB;
                uint32_t oh = sbase + ((st * 4 + 2) * PLANE + r * RSTR + ks * 8 + lwrdB) * 4;
                uint32_t ol = sbase + ((st * 4 + 3) * PLANE + r * RSTR + ks * 8 + lwrdB) * 4;
                uint32_t bh0, bh1, bh2, bh3, bl0, bl1, bl2, bl3;
                LDMX4(bh0, bh1, bh2, bh3, oh);
                LDMX4(bl0, bl1, bl2, bl3, ol);
                #pragma unroll
                for (int mt = 0; mt < 2; mt++) {
                    mma_bf16(acc[mt][2 * np],     ah[mt], bh0, bh1);
                    mma_bf16(acc[mt][2 * np],     ah[mt], bl0, bl1);
                    mma_bf16(acc[mt][2 * np],     al[mt], bh0, bh1);
                    mma_bf16(acc[mt][2 * np + 1], ah[mt], bh2, bh3);
                    mma_bf16(acc[mt][2 * np + 1], ah[mt], bl2, bl3);
                    mma_bf16(acc[mt][2 * np + 1], al[mt], bh2, bh3);
                }
            }
        }
    };

    issue_loads(0, 0);
    CPA_WAIT0();
    __syncthreads();

    for (int it = 0; it < iters; it++) {
        int cur = it & 1;
        if (it + 1 < iters) issue_loads(it + 1, cur ^ 1);
        compute(cur);
        CPA_WAIT0();
        __syncthreads();
    }

    float* C = g_acc2;
    #pragma unroll
    for (int mt = 0; mt < 2; mt++)
        #pragma unroll
        for (int nt = 0; nt < 8; nt++) {
            int r0 = m0 + wm * 32 + mt * 16 + g;
            int cc = n0 + wn * 64 + nt * 8 + t4 * 2;
            *(float2*)&C[(size_t)r0 * N + cc]       = make_float2(acc[mt][nt][0], acc[mt][nt][1]);
            *(float2*)&C[(size_t)(r0 + 8) * N + cc] = make_float2(acc[mt][nt][2], acc[mt][nt][3]);
        }
}

// ---------------- epilogue 1: reduce 6 partials + bias + relu + split ------------
__global__ void k_epi1(const float* __restrict__ fc0_b) {
    int idx = blockIdx.x * blockDim.x + threadIdx.x;
    if (idx >= NPADN * H1 / 4) return;
    int row = idx >> 6;
    int c4  = (idx & 63) * 4;
    float4 s = make_float4(0.f, 0.f, 0.f, 0.f);
    #pragma unroll
    for (int z = 0; z < 6; z++) {
        float4 p = *(const float4*)&g_part1[(size_t)z * MPAD * H1 + row * H1 + c4];
        s.x += p.x; s.y += p.y; s.z += p.z; s.w += p.w;
    }
    float4 b = *(const float4*)&fc0_b[c4];
    float z0 = fmaxf(s.x + b.x, 0.f), z1 = fmaxf(s.y + b.y, 0.f);
    float z2 = fmaxf(s.z + b.z, 0.f), z3 = fmaxf(s.w + b.w, 0.f);
    uint32_t h0, l0, h1, l1;
    split2x2(z0, z1, h0, l0);
    split2x2(z2, z3, h1, l1);
    *(uint2*)&g_Ahi[row * KCAT + c4] = make_uint2(h0, h1);
    *(uint2*)&g_Alo[row * KCAT + c4] = make_uint2(l0, l1);
}

// ---------------- LSTM pointwise + output projection -----------------------------
__global__ void k_lstm(const float* __restrict__ bg, const float* __restrict__ cb,
                       const float* __restrict__ c0,
                       const float* __restrict__ fc_w, const float* __restrict__ fc_b,
                       float* __restrict__ dout, int out_size) {
    __shared__ float red[4];
    int n = blockIdx.x;
    int o = threadIdx.x;
    const float* a = &g_acc2[(size_t)n * KCAT];
    float p0 = a[0 * H2 + o] + bg[0 * H2 + o] + cb[0 * H2 + o];
    float p1 = a[1 * H2 + o] + bg[1 * H2 + o] + cb[1 * H2 + o];
    float p2 = a[2 * H2 + o] + bg[2 * H2 + o] + cb[2 * H2 + o];
    float p3 = a[3 * H2 + o] + bg[3 * H2 + o] + cb[3 * H2 + o];
    float ig = sigmoidf_(p0);
    float fg = sigmoidf_(p1);
    float tg = tanhf(p2);
    float og = sigmoidf_(p3);
    float cn = fg * c0[n * H2 + o] + ig * tg;
    float hn = og * tanhf(cn);
    int hidx = NREAL + n * H2 + o;
    if (hidx < out_size) dout[hidx] = hn;

    float r = fmaxf(hn, 0.f) * fc_w[o];
    #pragma unroll
    for (int d = 16; d > 0; d >>= 1) r += __shfl_down_sync(0xffffffffu, r, d);
    int lane = o & 31, warp = o >> 5;
    if (lane == 0) red[warp] = r;
    __syncthreads();
    if (o == 0 && n < NREAL) {
        float s = red[0] + red[1] + red[2] + red[3] + fc_b[0];
        dout[n] = s;
    }
}

// ---------------- launch -----------------------------------------------------------
extern "C" void kernel_launch(void* const* d_in, const int* in_sizes, int n_in,
                              void* d_out, int out_size) {
    const float *x = nullptr, *ew = nullptr, *h0 = nullptr, *c0 = nullptr;
    const float *fc0w = nullptr, *fc0b = nullptr, *Wx = nullptr, *bg = nullptr;
    const float *cw0 = nullptr, *cw1 = nullptr, *cb = nullptr;
    const float *fcw = nullptr, *fcb = nullptr;
    const void* ei = nullptr;

    int pos384[2] = {-1, -1};
    int i256 = -1, iBigW = -1;

    for (int i = 0; i < n_in; i++) {
        int s = in_sizes[i];
        const void* p = d_in[i];
        if (s == NREAL * FIN)      x = (const float*)p;
        else if (s == 2 * NE)      ei = p;
        else if (s == NE)          ew = (const float*)p;
        else if (s == NPADN * H2)  { if (pos384[0] < 0) pos384[0] = i; else pos384[1] = i; }
        else if (s == FIN * H1)    { fc0w = (const float*)p; iBigW = i; }
        else if (s == H1)          { fc0b = (const float*)p; i256 = i; }
        else if (s == 4 * H1 * H2) Wx = (const float*)p;
        else if (s == 4 * H2)      { if (!bg) bg = (const float*)p; else cb = (const float*)p; }
        else if (s == 4 * H2 * H2) { if (!cw0) cw0 = (const float*)p; else cw1 = (const float*)p; }
        else if (s == H2)          fcw = (const float*)p;
        else if (s == 1)           fcb = (const float*)p;
    }

    bool sorted_order = (i256 >= 0 && iBigW >= 0 && i256 < iBigW);
    if (sorted_order) {
        c0 = (const float*)d_in[pos384[0]];
        h0 = (const float*)d_in[pos384[1]];
    } else {
        h0 = (const float*)d_in[pos384[0]];
        c0 = (const float*)d_in[pos384[1]];
    }

    float* out = (float*)d_out;

    cudaFuncSetAttribute(k_gemm1, cudaFuncAttributeMaxDynamicSharedMemorySize, SMEM1);
    cudaFuncSetAttribute(k_gemm2, cudaFuncAttributeMaxDynamicSharedMemorySize, SMEMSZ);

    // k_gemm1 at launch index 3 (ncu profile slot)
    k_probe_zero<<<(NPADN + 255) / 256, 256>>>(ei);            // 0
    k_convW<<<dim3(FIN / 32, H1 / 32), 256>>>(fc0w);           // 1
    k_buildB<<<(KCAT * KCAT + 255) / 256, 256>>>(Wx, cw0, cw1);// 2
    k_gemm1<<<dim3(24, 6), 512, SMEM1>>>(x);                   // 3  <- profiled
    k_edges1<<<(NE / 2 + 255) / 256, 256>>>(ei, ew);           // 4
    k_scan<<<1, 1024>>>();                                     // 5
    k_edges2<<<(NE + 255) / 256, 256>>>(ei, ew);               // 6
    k_T1<<<NPADN, H2>>>(h0);                                   // 7
    k_epi1<<<(NPADN * H1 / 4 + 255) / 256, 256>>>(fc0b);       // 8
    k_gemm2<<<dim3(24, 4), 256, SMEMSZ>>>();                   // 9
    k_lstm<<<NPADN, H2>>>(bg, cb, c0, fcw, fcb, out, out_size);// 10
}